// round 3
// baseline (speedup 1.0000x reference)
#include <cuda_runtime.h>
#include <math.h>

// Problem sizes
#define Bz 32
#define Sz 512
#define Iz 128
#define Hz 1024
#define Oz 128
#define TPB 256
#define SCAN_GRID 128

// Scratch (device globals)
__device__ float g_gates[(size_t)3 * Sz * Hz * Bz];   // [gate][t][j][b]
__device__ float g_seq[(size_t)Sz * Hz * Bz];         // [t][j][b]
__device__ float g_h[Hz * Bz];                        // [j][b]
__device__ float g_u[Hz * Bz];                        // [j][b]
__device__ int   g_bar[2 * Sz];
__device__ int   g_flag[2 * Sz];

__device__ __forceinline__ float sigmoidf_(float x) {
    return 1.0f / (1.0f + expf(-x));
}

// Grid barrier: fresh counter+flag per instance; single-writer release flag,
// read-only spin. Thread0's __threadfence (gpu scope) flushes/invalidates L1D,
// which also guarantees fresh g_h/g_u reads in the next phase.
__device__ __forceinline__ void grid_bar(int i, int ncta) {
    __syncthreads();
    if (threadIdx.x == 0) {
        __threadfence();
        int v = atomicAdd(&g_bar[i], 1);
        if (v == ncta - 1) {
            atomicExch(&g_flag[i], 1);
        } else {
            while (*(volatile int*)&g_flag[i] == 0) { }
        }
        __threadfence();
    }
    __syncthreads();
}

// ---------------------------------------------------------------------------
// prep: init h state (transposed) + zero barrier counters/flags
// ---------------------------------------------------------------------------
__global__ void prep_kernel(const float* __restrict__ h0, int layer) {
    int idx = blockIdx.x * TPB + threadIdx.x;
    int j = idx >> 5;
    int b = idx & 31;
    g_h[idx] = h0[b * (2 * Hz) + layer * Hz + j];
    if (idx < 2 * Sz) { g_bar[idx] = 0; g_flag[idx] = 0; }
}

// ---------------------------------------------------------------------------
// proj0: layer-0 input projections (K=128)
// ---------------------------------------------------------------------------
__global__ void __launch_bounds__(TPB) proj0_kernel(
    const float* __restrict__ x,
    const float* __restrict__ Wz, const float* __restrict__ Wr, const float* __restrict__ Wg)
{
    __shared__ float xs[Iz * 33];
    const int s = blockIdx.x;
    const int tid = threadIdx.x, lane = tid & 31, w = tid >> 5;

    #pragma unroll
    for (int rep = 0; rep < 16; ++rep) {
        int e = rep * 256 + tid;
        int b = e >> 7, i = e & 127;
        xs[i * 33 + b] = x[((size_t)b * Sz + s) * Iz + i];
    }
    __syncthreads();

    for (int c = 0; c < 96; ++c) {
        int rr = w * 384 + c * 4;
        int g = rr >> 10;
        int j = rr & 1023;
        const float* Wp = (g == 0) ? Wz : ((g == 1) ? Wr : Wg);
        const float4* w0 = (const float4*)(Wp + (size_t)(j + 0) * Iz);
        const float4* w1 = (const float4*)(Wp + (size_t)(j + 1) * Iz);
        const float4* w2 = (const float4*)(Wp + (size_t)(j + 2) * Iz);
        const float4* w3 = (const float4*)(Wp + (size_t)(j + 3) * Iz);
        float a0 = 0.f, a1 = 0.f, a2 = 0.f, a3 = 0.f;
        #pragma unroll 8
        for (int i4 = 0; i4 < 32; ++i4) {
            float h0v = xs[(i4 * 4 + 0) * 33 + lane];
            float h1v = xs[(i4 * 4 + 1) * 33 + lane];
            float h2v = xs[(i4 * 4 + 2) * 33 + lane];
            float h3v = xs[(i4 * 4 + 3) * 33 + lane];
            float4 q0 = w0[i4], q1 = w1[i4], q2 = w2[i4], q3 = w3[i4];
            a0 = fmaf(q0.x, h0v, a0); a0 = fmaf(q0.y, h1v, a0); a0 = fmaf(q0.z, h2v, a0); a0 = fmaf(q0.w, h3v, a0);
            a1 = fmaf(q1.x, h0v, a1); a1 = fmaf(q1.y, h1v, a1); a1 = fmaf(q1.z, h2v, a1); a1 = fmaf(q1.w, h3v, a1);
            a2 = fmaf(q2.x, h0v, a2); a2 = fmaf(q2.y, h1v, a2); a2 = fmaf(q2.z, h2v, a2); a2 = fmaf(q2.w, h3v, a2);
            a3 = fmaf(q3.x, h0v, a3); a3 = fmaf(q3.y, h1v, a3); a3 = fmaf(q3.z, h2v, a3); a3 = fmaf(q3.w, h3v, a3);
        }
        size_t base = (((size_t)g * Sz + s) * Hz + j) * Bz + lane;
        g_gates[base +  0] = a0;
        g_gates[base + 32] = a1;
        g_gates[base + 64] = a2;
        g_gates[base + 96] = a3;
    }
}

// ---------------------------------------------------------------------------
// proj1: layer-1 input projections (K=1024) from g_seq
// ---------------------------------------------------------------------------
__global__ void __launch_bounds__(TPB) proj1_kernel(
    const float* __restrict__ Wz, const float* __restrict__ Wr, const float* __restrict__ Wg)
{
    __shared__ float xs[256 * 33];
    const int s = blockIdx.y;
    const int rb = blockIdx.x;
    const int tid = threadIdx.x, lane = tid & 31, w = tid >> 5;

    float acc[48];
    #pragma unroll
    for (int q = 0; q < 48; ++q) acc[q] = 0.f;

    for (int kt = 0; kt < 4; ++kt) {
        __syncthreads();
        #pragma unroll
        for (int rep = 0; rep < 32; ++rep) {
            int e = rep * 256 + tid;
            int i = e >> 5, b = e & 31;
            xs[i * 33 + b] = g_seq[((size_t)s * Hz + kt * 256 + i) * Bz + b];
        }
        __syncthreads();
        #pragma unroll
        for (int c = 0; c < 12; ++c) {
            int rr = rb * 384 + w * 48 + c * 4;
            int g = rr >> 10, j = rr & 1023;
            const float* Wp = (g == 0) ? Wz : ((g == 1) ? Wr : Wg);
            const float4* w0 = (const float4*)(Wp + (size_t)(j + 0) * Hz + kt * 256);
            const float4* w1 = (const float4*)(Wp + (size_t)(j + 1) * Hz + kt * 256);
            const float4* w2 = (const float4*)(Wp + (size_t)(j + 2) * Hz + kt * 256);
            const float4* w3 = (const float4*)(Wp + (size_t)(j + 3) * Hz + kt * 256);
            float a0 = acc[c * 4 + 0], a1 = acc[c * 4 + 1];
            float a2 = acc[c * 4 + 2], a3 = acc[c * 4 + 3];
            #pragma unroll 8
            for (int i4 = 0; i4 < 64; ++i4) {
                float h0v = xs[(i4 * 4 + 0) * 33 + lane];
                float h1v = xs[(i4 * 4 + 1) * 33 + lane];
                float h2v = xs[(i4 * 4 + 2) * 33 + lane];
                float h3v = xs[(i4 * 4 + 3) * 33 + lane];
                float4 q0 = w0[i4], q1 = w1[i4], q2 = w2[i4], q3 = w3[i4];
                a0 = fmaf(q0.x, h0v, a0); a0 = fmaf(q0.y, h1v, a0); a0 = fmaf(q0.z, h2v, a0); a0 = fmaf(q0.w, h3v, a0);
                a1 = fmaf(q1.x, h0v, a1); a1 = fmaf(q1.y, h1v, a1); a1 = fmaf(q1.z, h2v, a1); a1 = fmaf(q1.w, h3v, a1);
                a2 = fmaf(q2.x, h0v, a2); a2 = fmaf(q2.y, h1v, a2); a2 = fmaf(q2.z, h2v, a2); a2 = fmaf(q2.w, h3v, a2);
                a3 = fmaf(q3.x, h0v, a3); a3 = fmaf(q3.y, h1v, a3); a3 = fmaf(q3.z, h2v, a3); a3 = fmaf(q3.w, h3v, a3);
            }
            acc[c * 4 + 0] = a0; acc[c * 4 + 1] = a1;
            acc[c * 4 + 2] = a2; acc[c * 4 + 3] = a3;
        }
    }
    #pragma unroll
    for (int c = 0; c < 12; ++c) {
        int rr = rb * 384 + w * 48 + c * 4;
        int g = rr >> 10, j = rr & 1023;
        size_t base = (((size_t)g * Sz + s) * Hz + j) * Bz + lane;
        g_gates[base +  0] = acc[c * 4 + 0];
        g_gates[base + 32] = acc[c * 4 + 1];
        g_gates[base + 64] = acc[c * 4 + 2];
        g_gates[base + 96] = acc[c * 4 + 3];
    }
}

// ---------------------------------------------------------------------------
// scan v3: weights CTA-stationary in SMEM; h/u read DIRECTLY from global in
// the compute loop (4-way intra-CTA reuse served by L1D — no smem staging,
// no STS, no staging syncs). 128 CTAs x 256 thr.
//
// SMEM: ws [3][8][1024] = 24576 floats, part [32][32] = 1024 floats.
// ---------------------------------------------------------------------------
#define SCAN_SMEM_FLOATS (24576 + 1024)

__global__ void __launch_bounds__(TPB) scan_kernel(
    const float* __restrict__ Whz, const float* __restrict__ Whr, const float* __restrict__ Whg,
    const float* __restrict__ bz,  const float* __restrict__ br,  const float* __restrict__ bg,
    float* __restrict__ hid_out, int layer)
{
    extern __shared__ float smem[];
    float* ws   = smem;            // 24576
    float* part = smem + 24576;    // 1024

    const int tid = threadIdx.x, lane = tid & 31, w = tid >> 5;
    const int jbase = blockIdx.x * 8;
    const int ncta = (int)gridDim.x;

    // ---- preload this CTA's weights (once per layer) ----------------------
    for (int idx = tid; idx < 6144; idx += TPB) {      // 6144 float4
        int g  = idx >> 11;
        int r2 = idx & 2047;
        int jl = r2 >> 8;
        int k4 = r2 & 255;
        const float* W = (g == 0) ? Whz : ((g == 1) ? Whr : Whg);
        float4 v = *(const float4*)(W + (size_t)(jbase + jl) * Hz + k4 * 4);
        *(float4*)&ws[((g * 8 + jl) << 10) + k4 * 4] = v;
    }
    __syncthreads();

    // reduction identity: thread owns (jr, bb)
    const int jr = w;
    const int jg = jbase + jr;
    const int bb = lane;
    const float bzj = bz[jg], brj = br[jg], bgj = bg[jg];
    const size_t plane = (size_t)Sz * Hz * Bz;

    // phase-1 mapping: warp = (j-pair jp, k-half khalf); 512 k per warp
    const int jp = w & 3, khalf = w >> 2;
    const int jl0 = 2 * jp, jl1 = 2 * jp + 1;
    const float4* wz0 = (const float4*)&ws[(0 * 8 + jl0) * 1024 + khalf * 512];
    const float4* wr0 = (const float4*)&ws[(1 * 8 + jl0) * 1024 + khalf * 512];
    const float4* wz1 = (const float4*)&ws[(0 * 8 + jl1) * 1024 + khalf * 512];
    const float4* wr1 = (const float4*)&ws[(1 * 8 + jl1) * 1024 + khalf * 512];
    const float* hp1 = &g_h[khalf * 512 * 32 + lane];

    // phase-2 mapping: warp = (j-quad jq, k-quarter kq); 256 k per warp
    const int jq = w & 1, kq = w >> 1;
    const float4* wg0 = (const float4*)&ws[(16 + 4 * jq + 0) * 1024 + kq * 256];
    const float4* wg1 = (const float4*)&ws[(16 + 4 * jq + 1) * 1024 + kq * 256];
    const float4* wg2 = (const float4*)&ws[(16 + 4 * jq + 2) * 1024 + kq * 256];
    const float4* wg3 = (const float4*)&ws[(16 + 4 * jq + 3) * 1024 + kq * 256];
    const float* up2 = &g_u[kq * 256 * 32 + lane];

    for (int t = 0; t < Sz; ++t) {
        const size_t gb = ((size_t)t * Hz + jg) * Bz + bb;
        // prefetch this step's z/r gate inputs + current h (hide DRAM/L2 latency)
        float gzv = g_gates[gb];
        float grv = g_gates[plane + gb];
        float hv  = g_h[jg * 32 + bb];

        // ================= phase 1: z, r, u = r*h =========================
        float az0 = 0.f, ar0 = 0.f, az1 = 0.f, ar1 = 0.f;
        #pragma unroll 8
        for (int i4 = 0; i4 < 128; ++i4) {
            float h0 = hp1[(i4 * 4 + 0) * 32];
            float h1 = hp1[(i4 * 4 + 1) * 32];
            float h2 = hp1[(i4 * 4 + 2) * 32];
            float h3 = hp1[(i4 * 4 + 3) * 32];
            float4 qz0 = wz0[i4], qr0 = wr0[i4], qz1 = wz1[i4], qr1 = wr1[i4];
            az0 = fmaf(qz0.x, h0, az0); az0 = fmaf(qz0.y, h1, az0); az0 = fmaf(qz0.z, h2, az0); az0 = fmaf(qz0.w, h3, az0);
            ar0 = fmaf(qr0.x, h0, ar0); ar0 = fmaf(qr0.y, h1, ar0); ar0 = fmaf(qr0.z, h2, ar0); ar0 = fmaf(qr0.w, h3, ar0);
            az1 = fmaf(qz1.x, h0, az1); az1 = fmaf(qz1.y, h1, az1); az1 = fmaf(qz1.z, h2, az1); az1 = fmaf(qz1.w, h3, az1);
            ar1 = fmaf(qr1.x, h0, ar1); ar1 = fmaf(qr1.y, h1, ar1); ar1 = fmaf(qr1.z, h2, ar1); ar1 = fmaf(qr1.w, h3, ar1);
        }
        part[(w * 4 + 0) * 32 + lane] = az0;
        part[(w * 4 + 1) * 32 + lane] = ar0;
        part[(w * 4 + 2) * 32 + lane] = az1;
        part[(w * 4 + 3) * 32 + lane] = ar1;
        __syncthreads();

        const int jp2 = jr >> 1, js = jr & 1;
        float zsum = part[(jp2 * 4 + js * 2 + 0) * 32 + bb]
                   + part[((jp2 + 4) * 4 + js * 2 + 0) * 32 + bb];
        float rsum = part[(jp2 * 4 + js * 2 + 1) * 32 + bb]
                   + part[((jp2 + 4) * 4 + js * 2 + 1) * 32 + bb];
        float zg = sigmoidf_(zsum + gzv + bzj);
        float rg = sigmoidf_(rsum + grv + brj);
        g_u[jg * 32 + bb] = rg * hv;

        grid_bar(2 * t, ncta);

        // prefetch g-gate input
        float ggv = g_gates[2 * plane + gb];

        // ================= phase 2: g, h_new ==============================
        float ag0 = 0.f, ag1 = 0.f, ag2 = 0.f, ag3 = 0.f;
        #pragma unroll 8
        for (int i4 = 0; i4 < 64; ++i4) {
            float h0 = up2[(i4 * 4 + 0) * 32];
            float h1 = up2[(i4 * 4 + 1) * 32];
            float h2 = up2[(i4 * 4 + 2) * 32];
            float h3 = up2[(i4 * 4 + 3) * 32];
            float4 q0 = wg0[i4], q1 = wg1[i4], q2 = wg2[i4], q3 = wg3[i4];
            ag0 = fmaf(q0.x, h0, ag0); ag0 = fmaf(q0.y, h1, ag0); ag0 = fmaf(q0.z, h2, ag0); ag0 = fmaf(q0.w, h3, ag0);
            ag1 = fmaf(q1.x, h0, ag1); ag1 = fmaf(q1.y, h1, ag1); ag1 = fmaf(q1.z, h2, ag1); ag1 = fmaf(q1.w, h3, ag1);
            ag2 = fmaf(q2.x, h0, ag2); ag2 = fmaf(q2.y, h1, ag2); ag2 = fmaf(q2.z, h2, ag2); ag2 = fmaf(q2.w, h3, ag2);
            ag3 = fmaf(q3.x, h0, ag3); ag3 = fmaf(q3.y, h1, ag3); ag3 = fmaf(q3.z, h2, ag3); ag3 = fmaf(q3.w, h3, ag3);
        }
        part[(w * 4 + 0) * 32 + lane] = ag0;
        part[(w * 4 + 1) * 32 + lane] = ag1;
        part[(w * 4 + 2) * 32 + lane] = ag2;
        part[(w * 4 + 3) * 32 + lane] = ag3;
        __syncthreads();

        const int jq2 = jr >> 2, jl3 = jr & 3;
        float gsum = part[((0 + jq2) * 4 + jl3) * 32 + bb]
                   + part[((2 + jq2) * 4 + jl3) * 32 + bb]
                   + part[((4 + jq2) * 4 + jl3) * 32 + bb]
                   + part[((6 + jq2) * 4 + jl3) * 32 + bb];
        float gv = tanhf(gsum + ggv + bgj);
        float hn = zg * hv + (1.0f - zg) * gv;
        g_h[jg * 32 + bb] = hn;
        g_seq[gb] = hn;
        if (t == Sz - 1) hid_out[bb * (2 * Hz) + layer * Hz + jg] = hn;

        grid_bar(2 * t + 1, ncta);
    }
}

// ---------------------------------------------------------------------------
// projY: y[b][s][o] = sum_h seq[s][h][b] * Wy[o][h] + by[o]
// ---------------------------------------------------------------------------
__global__ void __launch_bounds__(TPB) projy_kernel(
    const float* __restrict__ Wy, const float* __restrict__ by, float* __restrict__ y)
{
    __shared__ float xs[256 * 33];
    const int s = blockIdx.x;
    const int tid = threadIdx.x, lane = tid & 31, w = tid >> 5;

    float acc[16];
    #pragma unroll
    for (int q = 0; q < 16; ++q) acc[q] = 0.f;

    for (int kt = 0; kt < 4; ++kt) {
        __syncthreads();
        #pragma unroll
        for (int rep = 0; rep < 32; ++rep) {
            int e = rep * 256 + tid;
            int i = e >> 5, b = e & 31;
            xs[i * 33 + b] = g_seq[((size_t)s * Hz + kt * 256 + i) * Bz + b];
        }
        __syncthreads();
        #pragma unroll
        for (int c = 0; c < 4; ++c) {
            int o = w * 16 + c * 4;
            const float4* w0 = (const float4*)(Wy + (size_t)(o + 0) * Hz + kt * 256);
            const float4* w1 = (const float4*)(Wy + (size_t)(o + 1) * Hz + kt * 256);
            const float4* w2 = (const float4*)(Wy + (size_t)(o + 2) * Hz + kt * 256);
            const float4* w3 = (const float4*)(Wy + (size_t)(o + 3) * Hz + kt * 256);
            float a0 = acc[c * 4 + 0], a1 = acc[c * 4 + 1];
            float a2 = acc[c * 4 + 2], a3 = acc[c * 4 + 3];
            #pragma unroll 8
            for (int i4 = 0; i4 < 64; ++i4) {
                float h0v = xs[(i4 * 4 + 0) * 33 + lane];
                float h1v = xs[(i4 * 4 + 1) * 33 + lane];
                float h2v = xs[(i4 * 4 + 2) * 33 + lane];
                float h3v = xs[(i4 * 4 + 3) * 33 + lane];
                float4 q0 = w0[i4], q1 = w1[i4], q2 = w2[i4], q3 = w3[i4];
                a0 = fmaf(q0.x, h0v, a0); a0 = fmaf(q0.y, h1v, a0); a0 = fmaf(q0.z, h2v, a0); a0 = fmaf(q0.w, h3v, a0);
                a1 = fmaf(q1.x, h0v, a1); a1 = fmaf(q1.y, h1v, a1); a1 = fmaf(q1.z, h2v, a1); a1 = fmaf(q1.w, h3v, a1);
                a2 = fmaf(q2.x, h0v, a2); a2 = fmaf(q2.y, h1v, a2); a2 = fmaf(q2.z, h2v, a2); a2 = fmaf(q2.w, h3v, a2);
                a3 = fmaf(q3.x, h0v, a3); a3 = fmaf(q3.y, h1v, a3); a3 = fmaf(q3.z, h2v, a3); a3 = fmaf(q3.w, h3v, a3);
            }
            acc[c * 4 + 0] = a0; acc[c * 4 + 1] = a1;
            acc[c * 4 + 2] = a2; acc[c * 4 + 3] = a3;
        }
    }
    #pragma unroll
    for (int c = 0; c < 4; ++c) {
        #pragma unroll
        for (int q = 0; q < 4; ++q) {
            int o = w * 16 + c * 4 + q;
            y[(size_t)lane * (Sz * Oz) + (size_t)s * Oz + o] = acc[c * 4 + q] + by[o];
        }
    }
}

// ---------------------------------------------------------------------------
extern "C" void kernel_launch(void* const* d_in, const int* in_sizes, int n_in,
                              void* d_out, int out_size) {
    (void)in_sizes; (void)n_in; (void)out_size;
    const float* x    = (const float*)d_in[0];
    const float* h0   = (const float*)d_in[1];
    const float* Wxz0 = (const float*)d_in[2];
    const float* Whz0 = (const float*)d_in[3];
    const float* bz0  = (const float*)d_in[4];
    const float* Wxr0 = (const float*)d_in[5];
    const float* Whr0 = (const float*)d_in[6];
    const float* br0  = (const float*)d_in[7];
    const float* Wxg0 = (const float*)d_in[8];
    const float* Whg0 = (const float*)d_in[9];
    const float* bg0  = (const float*)d_in[10];
    const float* Wxz1 = (const float*)d_in[11];
    const float* Whz1 = (const float*)d_in[12];
    const float* bz1  = (const float*)d_in[13];
    const float* Wxr1 = (const float*)d_in[14];
    const float* Whr1 = (const float*)d_in[15];
    const float* br1  = (const float*)d_in[16];
    const float* Wxg1 = (const float*)d_in[17];
    const float* Whg1 = (const float*)d_in[18];
    const float* bg1  = (const float*)d_in[19];
    const float* Wy   = (const float*)d_in[20];
    const float* by   = (const float*)d_in[21];

    float* y   = (float*)d_out;
    float* hid = (float*)d_out + (size_t)Bz * Sz * Oz;

    const int scan_smem = SCAN_SMEM_FLOATS * (int)sizeof(float);
    cudaFuncSetAttribute(scan_kernel, cudaFuncAttributeMaxDynamicSharedMemorySize, scan_smem);

    // Layer 0
    proj0_kernel<<<Sz, TPB>>>(x, Wxz0, Wxr0, Wxg0);
    prep_kernel<<<SCAN_GRID, TPB>>>(h0, 0);
    scan_kernel<<<SCAN_GRID, TPB, scan_smem>>>(Whz0, Whr0, Whg0, bz0, br0, bg0, hid, 0);

    // Layer 1
    proj1_kernel<<<dim3(8, Sz), TPB>>>(Wxz1, Wxr1, Wxg1);
    prep_kernel<<<SCAN_GRID, TPB>>>(h0, 1);
    scan_kernel<<<SCAN_GRID, TPB, scan_smem>>>(Whz1, Whr1, Whg1, bz1, br1, bg1, hid, 1);

    // Output head
    projy_kernel<<<Sz, TPB>>>(Wy, by, y);
}

// round 4
// speedup vs baseline: 2.0193x; 2.0193x over previous
#include <cuda_runtime.h>
#include <math.h>

// Problem sizes
#define Bz 32
#define Sz 512
#define Iz 128
#define Hz 1024
#define Oz 128
#define TPB 256
#define TPBS 512
#define SCAN_GRID 128

typedef unsigned long long u64;

// Scratch (device globals)
__device__ __align__(16) float g_gates[(size_t)3 * Sz * Hz * Bz];   // [gate][t][j][b]
__device__ __align__(16) float g_seq[(size_t)Sz * Hz * Bz];         // [t][j][b]
__device__ __align__(16) float g_h[Hz * Bz];   // paired: [j/2][b][2] -> (j/2)*64 + 2b + (j&1)
__device__ __align__(16) float g_u[Hz * Bz];   // paired, same as g_h
__device__ int   g_bar[2 * Sz];
__device__ int   g_flag[2 * Sz];

__device__ __forceinline__ float sigmoidf_(float x) {
    return 1.0f / (1.0f + expf(-x));
}

// packed fp32x2 FMA: acc = a * b + acc (elementwise on 2 floats)
__device__ __forceinline__ void ffma2(u64& acc, u64 a, u64 b) {
    asm("fma.rn.f32x2 %0, %1, %2, %0;" : "+l"(acc) : "l"(a), "l"(b));
}
__device__ __forceinline__ float f2sum(u64 v) {
    float lo, hi;
    asm("mov.b64 {%0, %1}, %2;" : "=f"(lo), "=f"(hi) : "l"(v));
    return lo + hi;
}

// Grid barrier: fresh counter+flag per instance; single-writer release flag.
__device__ __forceinline__ void grid_bar(int i, int ncta) {
    __syncthreads();
    if (threadIdx.x == 0) {
        __threadfence();
        int v = atomicAdd(&g_bar[i], 1);
        if (v == ncta - 1) {
            atomicExch(&g_flag[i], 1);
        } else {
            while (*(volatile int*)&g_flag[i] == 0) { }
        }
        __threadfence();
    }
    __syncthreads();
}

// ---------------------------------------------------------------------------
// prep: init h state (paired layout) + zero barrier counters/flags
// ---------------------------------------------------------------------------
__global__ void prep_kernel(const float* __restrict__ h0, int layer) {
    int idx = blockIdx.x * TPB + threadIdx.x;
    int j = idx >> 5;
    int b = idx & 31;
    g_h[(j >> 1) * 64 + 2 * b + (j & 1)] = h0[b * (2 * Hz) + layer * Hz + j];
    if (idx < 2 * Sz) { g_bar[idx] = 0; g_flag[idx] = 0; }
}

// ---------------------------------------------------------------------------
// proj0: layer-0 input projections (K=128)
// ---------------------------------------------------------------------------
__global__ void __launch_bounds__(TPB) proj0_kernel(
    const float* __restrict__ x,
    const float* __restrict__ Wz, const float* __restrict__ Wr, const float* __restrict__ Wg)
{
    __shared__ float xs[Iz * 33];
    const int s = blockIdx.x;
    const int tid = threadIdx.x, lane = tid & 31, w = tid >> 5;

    #pragma unroll
    for (int rep = 0; rep < 16; ++rep) {
        int e = rep * 256 + tid;
        int b = e >> 7, i = e & 127;
        xs[i * 33 + b] = x[((size_t)b * Sz + s) * Iz + i];
    }
    __syncthreads();

    for (int c = 0; c < 96; ++c) {
        int rr = w * 384 + c * 4;
        int g = rr >> 10;
        int j = rr & 1023;
        const float* Wp = (g == 0) ? Wz : ((g == 1) ? Wr : Wg);
        const float4* w0 = (const float4*)(Wp + (size_t)(j + 0) * Iz);
        const float4* w1 = (const float4*)(Wp + (size_t)(j + 1) * Iz);
        const float4* w2 = (const float4*)(Wp + (size_t)(j + 2) * Iz);
        const float4* w3 = (const float4*)(Wp + (size_t)(j + 3) * Iz);
        float a0 = 0.f, a1 = 0.f, a2 = 0.f, a3 = 0.f;
        #pragma unroll 8
        for (int i4 = 0; i4 < 32; ++i4) {
            float h0v = xs[(i4 * 4 + 0) * 33 + lane];
            float h1v = xs[(i4 * 4 + 1) * 33 + lane];
            float h2v = xs[(i4 * 4 + 2) * 33 + lane];
            float h3v = xs[(i4 * 4 + 3) * 33 + lane];
            float4 q0 = w0[i4], q1 = w1[i4], q2 = w2[i4], q3 = w3[i4];
            a0 = fmaf(q0.x, h0v, a0); a0 = fmaf(q0.y, h1v, a0); a0 = fmaf(q0.z, h2v, a0); a0 = fmaf(q0.w, h3v, a0);
            a1 = fmaf(q1.x, h0v, a1); a1 = fmaf(q1.y, h1v, a1); a1 = fmaf(q1.z, h2v, a1); a1 = fmaf(q1.w, h3v, a1);
            a2 = fmaf(q2.x, h0v, a2); a2 = fmaf(q2.y, h1v, a2); a2 = fmaf(q2.z, h2v, a2); a2 = fmaf(q2.w, h3v, a2);
            a3 = fmaf(q3.x, h0v, a3); a3 = fmaf(q3.y, h1v, a3); a3 = fmaf(q3.z, h2v, a3); a3 = fmaf(q3.w, h3v, a3);
        }
        size_t base = (((size_t)g * Sz + s) * Hz + j) * Bz + lane;
        g_gates[base +  0] = a0;
        g_gates[base + 32] = a1;
        g_gates[base + 64] = a2;
        g_gates[base + 96] = a3;
    }
}

// ---------------------------------------------------------------------------
// proj1: layer-1 input projections (K=1024) from g_seq
// ---------------------------------------------------------------------------
__global__ void __launch_bounds__(TPB) proj1_kernel(
    const float* __restrict__ Wz, const float* __restrict__ Wr, const float* __restrict__ Wg)
{
    __shared__ float xs[256 * 33];
    const int s = blockIdx.y;
    const int rb = blockIdx.x;
    const int tid = threadIdx.x, lane = tid & 31, w = tid >> 5;

    float acc[48];
    #pragma unroll
    for (int q = 0; q < 48; ++q) acc[q] = 0.f;

    for (int kt = 0; kt < 4; ++kt) {
        __syncthreads();
        #pragma unroll
        for (int rep = 0; rep < 32; ++rep) {
            int e = rep * 256 + tid;
            int i = e >> 5, b = e & 31;
            xs[i * 33 + b] = g_seq[((size_t)s * Hz + kt * 256 + i) * Bz + b];
        }
        __syncthreads();
        #pragma unroll
        for (int c = 0; c < 12; ++c) {
            int rr = rb * 384 + w * 48 + c * 4;
            int g = rr >> 10, j = rr & 1023;
            const float* Wp = (g == 0) ? Wz : ((g == 1) ? Wr : Wg);
            const float4* w0 = (const float4*)(Wp + (size_t)(j + 0) * Hz + kt * 256);
            const float4* w1 = (const float4*)(Wp + (size_t)(j + 1) * Hz + kt * 256);
            const float4* w2 = (const float4*)(Wp + (size_t)(j + 2) * Hz + kt * 256);
            const float4* w3 = (const float4*)(Wp + (size_t)(j + 3) * Hz + kt * 256);
            float a0 = acc[c * 4 + 0], a1 = acc[c * 4 + 1];
            float a2 = acc[c * 4 + 2], a3 = acc[c * 4 + 3];
            #pragma unroll 8
            for (int i4 = 0; i4 < 64; ++i4) {
                float h0v = xs[(i4 * 4 + 0) * 33 + lane];
                float h1v = xs[(i4 * 4 + 1) * 33 + lane];
                float h2v = xs[(i4 * 4 + 2) * 33 + lane];
                float h3v = xs[(i4 * 4 + 3) * 33 + lane];
                float4 q0 = w0[i4], q1 = w1[i4], q2 = w2[i4], q3 = w3[i4];
                a0 = fmaf(q0.x, h0v, a0); a0 = fmaf(q0.y, h1v, a0); a0 = fmaf(q0.z, h2v, a0); a0 = fmaf(q0.w, h3v, a0);
                a1 = fmaf(q1.x, h0v, a1); a1 = fmaf(q1.y, h1v, a1); a1 = fmaf(q1.z, h2v, a1); a1 = fmaf(q1.w, h3v, a1);
                a2 = fmaf(q2.x, h0v, a2); a2 = fmaf(q2.y, h1v, a2); a2 = fmaf(q2.z, h2v, a2); a2 = fmaf(q2.w, h3v, a2);
                a3 = fmaf(q3.x, h0v, a3); a3 = fmaf(q3.y, h1v, a3); a3 = fmaf(q3.z, h2v, a3); a3 = fmaf(q3.w, h3v, a3);
            }
            acc[c * 4 + 0] = a0; acc[c * 4 + 1] = a1;
            acc[c * 4 + 2] = a2; acc[c * 4 + 3] = a3;
        }
    }
    #pragma unroll
    for (int c = 0; c < 12; ++c) {
        int rr = rb * 384 + w * 48 + c * 4;
        int g = rr >> 10, j = rr & 1023;
        size_t base = (((size_t)g * Sz + s) * Hz + j) * Bz + lane;
        g_gates[base +  0] = acc[c * 4 + 0];
        g_gates[base + 32] = acc[c * 4 + 1];
        g_gates[base + 64] = acc[c * 4 + 2];
        g_gates[base + 96] = acc[c * 4 + 3];
    }
}

// ---------------------------------------------------------------------------
// scan v4: 512 threads (16 warps), weights smem-stationary, state in paired
// [k/2][b][2] layout, packed fp32x2 FFMA (k-parity packing), 2-tile staging
// with pure float4 copies. 128 CTAs.
//
// SMEM: ws 24576 | ht 16384 (512k x 32b tile) | part 2048  = 43008 floats (168KB)
// ---------------------------------------------------------------------------
#define SCAN_SMEM_FLOATS (24576 + 16384 + 2048)

__global__ void __launch_bounds__(TPBS, 1) scan_kernel(
    const float* __restrict__ Whz, const float* __restrict__ Whr, const float* __restrict__ Whg,
    const float* __restrict__ bz,  const float* __restrict__ br,  const float* __restrict__ bg,
    float* __restrict__ hid_out, int layer)
{
    extern __shared__ float smem[];
    float* ws   = smem;            // [24 rows][1024]  (z:0-7, r:8-15, g:16-23)
    float* ht   = smem + 24576;    // tile: 256 k-pairs x [b][2]
    float* part = smem + 24576 + 16384;  // [16 warps][4][32]

    const int tid = threadIdx.x, lane = tid & 31, w = tid >> 5;
    const int jbase = blockIdx.x * 8;
    const int ncta = (int)gridDim.x;

    // ---- preload weights (once per layer): 6144 float4 --------------------
    for (int idx = tid; idx < 6144; idx += TPBS) {
        int g  = idx >> 11;
        int r2 = idx & 2047;
        int jl = r2 >> 8;
        int k4 = r2 & 255;
        const float* W = (g == 0) ? Whz : ((g == 1) ? Whr : Whg);
        float4 v = *(const float4*)(W + (size_t)(jbase + jl) * Hz + k4 * 4);
        *(float4*)&ws[((g * 8 + jl) << 10) + k4 * 4] = v;
    }
    __syncthreads();

    // reduction identity (warps 0..7): thread owns (jr, bb)
    const int jr = w & 7;
    const int jg = jbase + jr;
    const int bb = lane;
    const float bzj = bz[jg], brj = br[jg], bgj = bg[jg];
    const size_t plane = (size_t)Sz * Hz * Bz;
    const int pidx = (jg >> 1) * 64 + 2 * bb + (jg & 1);   // paired state index

    // compute mapping (both phases): warp = (j-pair jp, k-slice sub)
    const int jp = w & 3, sub = w >> 2;   // jp: 0..3, sub: 0..3 (128 k per tile-slice)
    // weight row bases
    const float* wzr0 = &ws[(0 + 2 * jp)     * 1024];
    const float* wzr1 = &ws[(0 + 2 * jp + 1) * 1024];
    const float* wrr0 = &ws[(8 + 2 * jp)     * 1024];
    const float* wrr1 = &ws[(8 + 2 * jp + 1) * 1024];
    const float* wgr0 = &ws[(16 + 2 * jp)     * 1024];
    const float* wgr1 = &ws[(16 + 2 * jp + 1) * 1024];
    // h-tile pointer for this warp's slice: pair index (sub*64 + i), lane b
    const u64* hq = (const u64*)&ht[(sub * 64) * 64 + 2 * lane];   // stride 32 u64 per pair

    for (int t = 0; t < Sz; ++t) {
        const size_t gb = ((size_t)t * Hz + jg) * Bz + bb;
        float gzv = 0.f, grv = 0.f, hv = 0.f, zg = 0.f, rg = 0.f;
        if (w < 8) {            // prefetch gate inputs + current h
            gzv = g_gates[gb];
            grv = g_gates[plane + gb];
            hv  = g_h[pidx];
        }

        // ================= phase 1: z, r, u = r*h =========================
        u64 az0 = 0ull, az1 = 0ull, ar0 = 0ull, ar1 = 0ull;
        #pragma unroll
        for (int tile = 0; tile < 2; ++tile) {
            __syncthreads();
            {   // stage 64KB: g_h[tile*16384 .. +16384) -> ht (linear copy)
                const float4* src = (const float4*)&g_h[tile * 16384];
                float4* dst = (float4*)ht;
                #pragma unroll
                for (int r = 0; r < 8; ++r) dst[r * TPBS + tid] = src[r * TPBS + tid];
            }
            __syncthreads();
            const int kg = tile * 512 + sub * 128;
            const ulonglong2* wz0 = (const ulonglong2*)(wzr0 + kg);
            const ulonglong2* wz1 = (const ulonglong2*)(wzr1 + kg);
            const ulonglong2* wr0 = (const ulonglong2*)(wrr0 + kg);
            const ulonglong2* wr1 = (const ulonglong2*)(wrr1 + kg);
            #pragma unroll 4
            for (int ii = 0; ii < 32; ++ii) {
                u64 hA = hq[(2 * ii + 0) * 32];
                u64 hB = hq[(2 * ii + 1) * 32];
                ulonglong2 qz0 = wz0[ii], qz1 = wz1[ii], qr0 = wr0[ii], qr1 = wr1[ii];
                ffma2(az0, qz0.x, hA); ffma2(az0, qz0.y, hB);
                ffma2(az1, qz1.x, hA); ffma2(az1, qz1.y, hB);
                ffma2(ar0, qr0.x, hA); ffma2(ar0, qr0.y, hB);
                ffma2(ar1, qr1.x, hA); ffma2(ar1, qr1.y, hB);
            }
        }
        part[(w * 4 + 0) * 32 + lane] = f2sum(az0);
        part[(w * 4 + 1) * 32 + lane] = f2sum(az1);
        part[(w * 4 + 2) * 32 + lane] = f2sum(ar0);
        part[(w * 4 + 3) * 32 + lane] = f2sum(ar1);
        __syncthreads();

        if (w < 8) {
            const int wb = jr >> 1, sl = jr & 1;   // partial stream for this j
            float zsum = 0.f, rsum = 0.f;
            #pragma unroll
            for (int sb = 0; sb < 4; ++sb) {
                int W4 = ((sb << 2) | wb) * 4;
                zsum += part[(W4 + 0 + sl) * 32 + bb];
                rsum += part[(W4 + 2 + sl) * 32 + bb];
            }
            zg = sigmoidf_(zsum + gzv + bzj);
            rg = sigmoidf_(rsum + grv + brj);
            g_u[pidx] = rg * hv;
        }

        grid_bar(2 * t, ncta);

        float ggv = 0.f;
        if (w < 8) ggv = g_gates[2 * plane + gb];

        // ================= phase 2: g, h_new ==============================
        u64 ag0 = 0ull, ag1 = 0ull;
        #pragma unroll
        for (int tile = 0; tile < 2; ++tile) {
            __syncthreads();
            {
                const float4* src = (const float4*)&g_u[tile * 16384];
                float4* dst = (float4*)ht;
                #pragma unroll
                for (int r = 0; r < 8; ++r) dst[r * TPBS + tid] = src[r * TPBS + tid];
            }
            __syncthreads();
            const int kg = tile * 512 + sub * 128;
            const ulonglong2* wg0 = (const ulonglong2*)(wgr0 + kg);
            const ulonglong2* wg1 = (const ulonglong2*)(wgr1 + kg);
            #pragma unroll 4
            for (int ii = 0; ii < 32; ++ii) {
                u64 hA = hq[(2 * ii + 0) * 32];
                u64 hB = hq[(2 * ii + 1) * 32];
                ulonglong2 q0 = wg0[ii], q1 = wg1[ii];
                ffma2(ag0, q0.x, hA); ffma2(ag0, q0.y, hB);
                ffma2(ag1, q1.x, hA); ffma2(ag1, q1.y, hB);
            }
        }
        part[(w * 4 + 0) * 32 + lane] = f2sum(ag0);
        part[(w * 4 + 1) * 32 + lane] = f2sum(ag1);
        __syncthreads();

        if (w < 8) {
            const int wb = jr >> 1, sl = jr & 1;
            float gsum = 0.f;
            #pragma unroll
            for (int sb = 0; sb < 4; ++sb) {
                int W4 = ((sb << 2) | wb) * 4;
                gsum += part[(W4 + sl) * 32 + bb];
            }
            float gv = tanhf(gsum + ggv + bgj);
            float hn = zg * hv + (1.0f - zg) * gv;
            g_h[pidx] = hn;
            g_seq[gb] = hn;
            if (t == Sz - 1) hid_out[bb * (2 * Hz) + layer * Hz + jg] = hn;
        }

        grid_bar(2 * t + 1, ncta);
    }
}

// ---------------------------------------------------------------------------
// projY: y[b][s][o] = sum_h seq[s][h][b] * Wy[o][h] + by[o]
// ---------------------------------------------------------------------------
__global__ void __launch_bounds__(TPB) projy_kernel(
    const float* __restrict__ Wy, const float* __restrict__ by, float* __restrict__ y)
{
    __shared__ float xs[256 * 33];
    const int s = blockIdx.x;
    const int tid = threadIdx.x, lane = tid & 31, w = tid >> 5;

    float acc[16];
    #pragma unroll
    for (int q = 0; q < 16; ++q) acc[q] = 0.f;

    for (int kt = 0; kt < 4; ++kt) {
        __syncthreads();
        #pragma unroll
        for (int rep = 0; rep < 32; ++rep) {
            int e = rep * 256 + tid;
            int i = e >> 5, b = e & 31;
            xs[i * 33 + b] = g_seq[((size_t)s * Hz + kt * 256 + i) * Bz + b];
        }
        __syncthreads();
        #pragma unroll
        for (int c = 0; c < 4; ++c) {
            int o = w * 16 + c * 4;
            const float4* w0 = (const float4*)(Wy + (size_t)(o + 0) * Hz + kt * 256);
            const float4* w1 = (const float4*)(Wy + (size_t)(o + 1) * Hz + kt * 256);
            const float4* w2 = (const float4*)(Wy + (size_t)(o + 2) * Hz + kt * 256);
            const float4* w3 = (const float4*)(Wy + (size_t)(o + 3) * Hz + kt * 256);
            float a0 = acc[c * 4 + 0], a1 = acc[c * 4 + 1];
            float a2 = acc[c * 4 + 2], a3 = acc[c * 4 + 3];
            #pragma unroll 8
            for (int i4 = 0; i4 < 64; ++i4) {
                float h0v = xs[(i4 * 4 + 0) * 33 + lane];
                float h1v = xs[(i4 * 4 + 1) * 33 + lane];
                float h2v = xs[(i4 * 4 + 2) * 33 + lane];
                float h3v = xs[(i4 * 4 + 3) * 33 + lane];
                float4 q0 = w0[i4], q1 = w1[i4], q2 = w2[i4], q3 = w3[i4];
                a0 = fmaf(q0.x, h0v, a0); a0 = fmaf(q0.y, h1v, a0); a0 = fmaf(q0.z, h2v, a0); a0 = fmaf(q0.w, h3v, a0);
                a1 = fmaf(q1.x, h0v, a1); a1 = fmaf(q1.y, h1v, a1); a1 = fmaf(q1.z, h2v, a1); a1 = fmaf(q1.w, h3v, a1);
                a2 = fmaf(q2.x, h0v, a2); a2 = fmaf(q2.y, h1v, a2); a2 = fmaf(q2.z, h2v, a2); a2 = fmaf(q2.w, h3v, a2);
                a3 = fmaf(q3.x, h0v, a3); a3 = fmaf(q3.y, h1v, a3); a3 = fmaf(q3.z, h2v, a3); a3 = fmaf(q3.w, h3v, a3);
            }
            acc[c * 4 + 0] = a0; acc[c * 4 + 1] = a1;
            acc[c * 4 + 2] = a2; acc[c * 4 + 3] = a3;
        }
    }
    #pragma unroll
    for (int c = 0; c < 4; ++c) {
        #pragma unroll
        for (int q = 0; q < 4; ++q) {
            int o = w * 16 + c * 4 + q;
            y[(size_t)lane * (Sz * Oz) + (size_t)s * Oz + o] = acc[c * 4 + q] + by[o];
        }
    }
}

// ---------------------------------------------------------------------------
extern "C" void kernel_launch(void* const* d_in, const int* in_sizes, int n_in,
                              void* d_out, int out_size) {
    (void)in_sizes; (void)n_in; (void)out_size;
    const float* x    = (const float*)d_in[0];
    const float* h0   = (const float*)d_in[1];
    const float* Wxz0 = (const float*)d_in[2];
    const float* Whz0 = (const float*)d_in[3];
    const float* bz0  = (const float*)d_in[4];
    const float* Wxr0 = (const float*)d_in[5];
    const float* Whr0 = (const float*)d_in[6];
    const float* br0  = (const float*)d_in[7];
    const float* Wxg0 = (const float*)d_in[8];
    const float* Whg0 = (const float*)d_in[9];
    const float* bg0  = (const float*)d_in[10];
    const float* Wxz1 = (const float*)d_in[11];
    const float* Whz1 = (const float*)d_in[12];
    const float* bz1  = (const float*)d_in[13];
    const float* Wxr1 = (const float*)d_in[14];
    const float* Whr1 = (const float*)d_in[15];
    const float* br1  = (const float*)d_in[16];
    const float* Wxg1 = (const float*)d_in[17];
    const float* Whg1 = (const float*)d_in[18];
    const float* bg1  = (const float*)d_in[19];
    const float* Wy   = (const float*)d_in[20];
    const float* by   = (const float*)d_in[21];

    float* y   = (float*)d_out;
    float* hid = (float*)d_out + (size_t)Bz * Sz * Oz;

    const int scan_smem = SCAN_SMEM_FLOATS * (int)sizeof(float);
    cudaFuncSetAttribute(scan_kernel, cudaFuncAttributeMaxDynamicSharedMemorySize, scan_smem);

    // Layer 0
    proj0_kernel<<<Sz, TPB>>>(x, Wxz0, Wxr0, Wxg0);
    prep_kernel<<<SCAN_GRID, TPB>>>(h0, 0);
    scan_kernel<<<SCAN_GRID, TPBS, scan_smem>>>(Whz0, Whr0, Whg0, bz0, br0, bg0, hid, 0);

    // Layer 1
    proj1_kernel<<<dim3(8, Sz), TPB>>>(Wxz1, Wxr1, Wxg1);
    prep_kernel<<<SCAN_GRID, TPB>>>(h0, 1);
    scan_kernel<<<SCAN_GRID, TPBS, scan_smem>>>(Whz1, Whr1, Whg1, bz1, br1, bg1, hid, 1);

    // Output head
    projy_kernel<<<Sz, TPB>>>(Wy, by, y);
}

// round 5
// speedup vs baseline: 2.1325x; 1.0560x over previous
#include <cuda_runtime.h>
#include <math.h>

// Problem sizes
#define Bz 32
#define Sz 512
#define Iz 128
#define Hz 1024
#define Oz 128
#define TPB 256
#define TPBS 512
#define SCAN_GRID 128

typedef unsigned long long u64;

// Scratch (device globals)
__device__ __align__(16) float g_gates[(size_t)3 * Sz * Hz * Bz];   // [gate][t][j][b]
__device__ __align__(16) float g_seq[(size_t)Sz * Hz * Bz];         // [t][j][b]
__device__ __align__(16) float g_h[Hz * Bz];   // paired: [j/2][b][2] -> (j/2)*64 + 2b + (j&1)
__device__ __align__(16) float g_u[Hz * Bz];   // paired, same as g_h
__device__ int   g_bar[2 * Sz];
__device__ int   g_flag[2 * Sz];

__device__ __forceinline__ float sigmoidf_(float x) {
    return 1.0f / (1.0f + expf(-x));
}

// packed fp32x2 FMA: acc = a * b + acc
__device__ __forceinline__ void ffma2(u64& acc, u64 a, u64 b) {
    asm("fma.rn.f32x2 %0, %1, %2, %0;" : "+l"(acc) : "l"(a), "l"(b));
}
__device__ __forceinline__ float f2sum(u64 v) {
    float lo, hi;
    asm("mov.b64 {%0, %1}, %2;" : "=f"(lo), "=f"(hi) : "l"(v));
    return lo + hi;
}

// cp.async 16B, L1-bypass (.cg): all cross-CTA state flows through L2 only.
__device__ __forceinline__ void cpa16(unsigned s, const void* g) {
    asm volatile("cp.async.cg.shared.global [%0], [%1], 16;" :: "r"(s), "l"(g));
}
__device__ __forceinline__ void cpa_commit() {
    asm volatile("cp.async.commit_group;" ::: "memory");
}
template <int N>
__device__ __forceinline__ void cpa_wait() {
    asm volatile("cp.async.wait_group %0;" :: "n"(N) : "memory");
}

// Fence-free grid barrier: release-atomic arrive, single-writer release flag,
// acquire spin. No __threadfence => no CCTL.IVALL. Safe because all cross-CTA
// data reads bypass L1 (cp.async.cg), so only L2 ordering (release/acquire)
// is required.
__device__ __forceinline__ void grid_bar(int i, int ncta) {
    __syncthreads();
    if (threadIdx.x == 0) {
        int v;
        asm volatile("atom.release.gpu.global.add.s32 %0, [%1], 1;"
                     : "=r"(v) : "l"(&g_bar[i]) : "memory");
        if (v == ncta - 1) {
            asm volatile("st.release.gpu.global.s32 [%0], 1;"
                         :: "l"(&g_flag[i]) : "memory");
        } else {
            int f;
            do {
                asm volatile("ld.acquire.gpu.global.s32 %0, [%1];"
                             : "=r"(f) : "l"(&g_flag[i]) : "memory");
            } while (f == 0);
        }
    }
    __syncthreads();
}

// ---------------------------------------------------------------------------
// prep: init h state (paired layout) + zero barrier counters/flags
// ---------------------------------------------------------------------------
__global__ void prep_kernel(const float* __restrict__ h0, int layer) {
    int idx = blockIdx.x * TPB + threadIdx.x;
    int j = idx >> 5;
    int b = idx & 31;
    g_h[(j >> 1) * 64 + 2 * b + (j & 1)] = h0[b * (2 * Hz) + layer * Hz + j];
    if (idx < 2 * Sz) { g_bar[idx] = 0; g_flag[idx] = 0; }
}

// ---------------------------------------------------------------------------
// proj0: layer-0 input projections (K=128)
// ---------------------------------------------------------------------------
__global__ void __launch_bounds__(TPB) proj0_kernel(
    const float* __restrict__ x,
    const float* __restrict__ Wz, const float* __restrict__ Wr, const float* __restrict__ Wg)
{
    __shared__ float xs[Iz * 33];
    const int s = blockIdx.x;
    const int tid = threadIdx.x, lane = tid & 31, w = tid >> 5;

    #pragma unroll
    for (int rep = 0; rep < 16; ++rep) {
        int e = rep * 256 + tid;
        int b = e >> 7, i = e & 127;
        xs[i * 33 + b] = x[((size_t)b * Sz + s) * Iz + i];
    }
    __syncthreads();

    for (int c = 0; c < 96; ++c) {
        int rr = w * 384 + c * 4;
        int g = rr >> 10;
        int j = rr & 1023;
        const float* Wp = (g == 0) ? Wz : ((g == 1) ? Wr : Wg);
        const float4* w0 = (const float4*)(Wp + (size_t)(j + 0) * Iz);
        const float4* w1 = (const float4*)(Wp + (size_t)(j + 1) * Iz);
        const float4* w2 = (const float4*)(Wp + (size_t)(j + 2) * Iz);
        const float4* w3 = (const float4*)(Wp + (size_t)(j + 3) * Iz);
        float a0 = 0.f, a1 = 0.f, a2 = 0.f, a3 = 0.f;
        #pragma unroll 8
        for (int i4 = 0; i4 < 32; ++i4) {
            float h0v = xs[(i4 * 4 + 0) * 33 + lane];
            float h1v = xs[(i4 * 4 + 1) * 33 + lane];
            float h2v = xs[(i4 * 4 + 2) * 33 + lane];
            float h3v = xs[(i4 * 4 + 3) * 33 + lane];
            float4 q0 = w0[i4], q1 = w1[i4], q2 = w2[i4], q3 = w3[i4];
            a0 = fmaf(q0.x, h0v, a0); a0 = fmaf(q0.y, h1v, a0); a0 = fmaf(q0.z, h2v, a0); a0 = fmaf(q0.w, h3v, a0);
            a1 = fmaf(q1.x, h0v, a1); a1 = fmaf(q1.y, h1v, a1); a1 = fmaf(q1.z, h2v, a1); a1 = fmaf(q1.w, h3v, a1);
            a2 = fmaf(q2.x, h0v, a2); a2 = fmaf(q2.y, h1v, a2); a2 = fmaf(q2.z, h2v, a2); a2 = fmaf(q2.w, h3v, a2);
            a3 = fmaf(q3.x, h0v, a3); a3 = fmaf(q3.y, h1v, a3); a3 = fmaf(q3.z, h2v, a3); a3 = fmaf(q3.w, h3v, a3);
        }
        size_t base = (((size_t)g * Sz + s) * Hz + j) * Bz + lane;
        g_gates[base +  0] = a0;
        g_gates[base + 32] = a1;
        g_gates[base + 64] = a2;
        g_gates[base + 96] = a3;
    }
}

// ---------------------------------------------------------------------------
// proj1: layer-1 input projections (K=1024) from g_seq
// ---------------------------------------------------------------------------
__global__ void __launch_bounds__(TPB) proj1_kernel(
    const float* __restrict__ Wz, const float* __restrict__ Wr, const float* __restrict__ Wg)
{
    __shared__ float xs[256 * 33];
    const int s = blockIdx.y;
    const int rb = blockIdx.x;
    const int tid = threadIdx.x, lane = tid & 31, w = tid >> 5;

    float acc[48];
    #pragma unroll
    for (int q = 0; q < 48; ++q) acc[q] = 0.f;

    for (int kt = 0; kt < 4; ++kt) {
        __syncthreads();
        #pragma unroll
        for (int rep = 0; rep < 32; ++rep) {
            int e = rep * 256 + tid;
            int i = e >> 5, b = e & 31;
            xs[i * 33 + b] = g_seq[((size_t)s * Hz + kt * 256 + i) * Bz + b];
        }
        __syncthreads();
        #pragma unroll
        for (int c = 0; c < 12; ++c) {
            int rr = rb * 384 + w * 48 + c * 4;
            int g = rr >> 10, j = rr & 1023;
            const float* Wp = (g == 0) ? Wz : ((g == 1) ? Wr : Wg);
            const float4* w0 = (const float4*)(Wp + (size_t)(j + 0) * Hz + kt * 256);
            const float4* w1 = (const float4*)(Wp + (size_t)(j + 1) * Hz + kt * 256);
            const float4* w2 = (const float4*)(Wp + (size_t)(j + 2) * Hz + kt * 256);
            const float4* w3 = (const float4*)(Wp + (size_t)(j + 3) * Hz + kt * 256);
            float a0 = acc[c * 4 + 0], a1 = acc[c * 4 + 1];
            float a2 = acc[c * 4 + 2], a3 = acc[c * 4 + 3];
            #pragma unroll 8
            for (int i4 = 0; i4 < 64; ++i4) {
                float h0v = xs[(i4 * 4 + 0) * 33 + lane];
                float h1v = xs[(i4 * 4 + 1) * 33 + lane];
                float h2v = xs[(i4 * 4 + 2) * 33 + lane];
                float h3v = xs[(i4 * 4 + 3) * 33 + lane];
                float4 q0 = w0[i4], q1 = w1[i4], q2 = w2[i4], q3 = w3[i4];
                a0 = fmaf(q0.x, h0v, a0); a0 = fmaf(q0.y, h1v, a0); a0 = fmaf(q0.z, h2v, a0); a0 = fmaf(q0.w, h3v, a0);
                a1 = fmaf(q1.x, h0v, a1); a1 = fmaf(q1.y, h1v, a1); a1 = fmaf(q1.z, h2v, a1); a1 = fmaf(q1.w, h3v, a1);
                a2 = fmaf(q2.x, h0v, a2); a2 = fmaf(q2.y, h1v, a2); a2 = fmaf(q2.z, h2v, a2); a2 = fmaf(q2.w, h3v, a2);
                a3 = fmaf(q3.x, h0v, a3); a3 = fmaf(q3.y, h1v, a3); a3 = fmaf(q3.z, h2v, a3); a3 = fmaf(q3.w, h3v, a3);
            }
            acc[c * 4 + 0] = a0; acc[c * 4 + 1] = a1;
            acc[c * 4 + 2] = a2; acc[c * 4 + 3] = a3;
        }
    }
    #pragma unroll
    for (int c = 0; c < 12; ++c) {
        int rr = rb * 384 + w * 48 + c * 4;
        int g = rr >> 10, j = rr & 1023;
        size_t base = (((size_t)g * Sz + s) * Hz + j) * Bz + lane;
        g_gates[base +  0] = acc[c * 4 + 0];
        g_gates[base + 32] = acc[c * 4 + 1];
        g_gates[base + 64] = acc[c * 4 + 2];
        g_gates[base + 96] = acc[c * 4 + 3];
    }
}

// ---------------------------------------------------------------------------
// scan v5: double-buffered cp.async.cg staging (4 tiles of 32KB per phase),
// fence-free release/acquire grid barrier, packed fp32x2 FFMA.
// 128 CTAs x 512 threads.
//
// SMEM layout (floats): buf0 8192 | buf1 8192 | ws 24576 | part 2048 = 43008
// ---------------------------------------------------------------------------
#define SCAN_SMEM_FLOATS (8192 + 8192 + 24576 + 2048)
#define TILE_FLOATS 8192   // 128 k-pairs x [b][2] = 32KB

__global__ void __launch_bounds__(TPBS, 1) scan_kernel(
    const float* __restrict__ Whz, const float* __restrict__ Whr, const float* __restrict__ Whg,
    const float* __restrict__ bz,  const float* __restrict__ br,  const float* __restrict__ bg,
    float* __restrict__ hid_out, int layer)
{
    extern __shared__ float smem[];
    float* bufs = smem;                    // 2 x 8192
    float* ws   = smem + 2 * TILE_FLOATS;  // 24576  (z:0-7, r:8-15, g:16-23)
    float* part = ws + 24576;              // [16 warps][4][32]

    const int tid = threadIdx.x, lane = tid & 31, w = tid >> 5;
    const int jbase = blockIdx.x * 8;
    const int ncta = (int)gridDim.x;

    unsigned sbase;
    asm("{.reg .u64 t; cvta.to.shared.u64 t, %1; cvt.u32.u64 %0, t;}"
        : "=r"(sbase) : "l"(smem));
    const unsigned buf_s[2] = { sbase, sbase + TILE_FLOATS * 4u };
    const unsigned cp_off = (unsigned)tid * 16u;

    // ---- preload weights (once per layer): 6144 float4 --------------------
    for (int idx = tid; idx < 6144; idx += TPBS) {
        int g  = idx >> 11;
        int r2 = idx & 2047;
        int jl = r2 >> 8;
        int k4 = r2 & 255;
        const float* W = (g == 0) ? Whz : ((g == 1) ? Whr : Whg);
        float4 v = *(const float4*)(W + (size_t)(jbase + jl) * Hz + k4 * 4);
        *(float4*)&ws[((g * 8 + jl) << 10) + k4 * 4] = v;
    }
    __syncthreads();

    // reduction identity (warps 0..7): thread owns (jr, bb)
    const int jr = w & 7;
    const int jg = jbase + jr;
    const int bb = lane;
    const float bzj = bz[jg], brj = br[jg], bgj = bg[jg];
    const size_t plane = (size_t)Sz * Hz * Bz;
    const int pidx = (jg >> 1) * 64 + 2 * bb + (jg & 1);

    // compute mapping: warp = (j-pair jp, k-slice sub); per tile each warp
    // covers 32 k-pairs (64 k).
    const int jp = w & 3, sub = w >> 2;
    const float* wzr0 = &ws[(0 + 2 * jp)      * 1024];
    const float* wzr1 = &ws[(0 + 2 * jp + 1)  * 1024];
    const float* wrr0 = &ws[(8 + 2 * jp)      * 1024];
    const float* wrr1 = &ws[(8 + 2 * jp + 1)  * 1024];
    const float* wgr0 = &ws[(16 + 2 * jp)     * 1024];
    const float* wgr1 = &ws[(16 + 2 * jp + 1) * 1024];
    // per-warp h pointers into each buffer: pair (sub*32 + i), lane b
    const u64* hq[2] = {
        (const u64*)&bufs[(sub * 32) * 64 + 2 * lane],
        (const u64*)&bufs[TILE_FLOATS + (sub * 32) * 64 + 2 * lane]
    };

    for (int t = 0; t < Sz; ++t) {
        const size_t gb = ((size_t)t * Hz + jg) * Bz + bb;
        float gzv = 0.f, grv = 0.f, hv = 0.f, zg = 0.f, rg = 0.f;
        if (w < 8) {
            gzv = g_gates[gb];
            grv = g_gates[plane + gb];
            hv  = g_h[pidx];
        }

        // ================= phase 1: z, r, u = r*h =========================
        u64 az0 = 0ull, az1 = 0ull, ar0 = 0ull, ar1 = 0ull;
        // prime tile 0
        #pragma unroll
        for (int c = 0; c < 4; ++c)
            cpa16(buf_s[0] + cp_off + c * 8192u, (const char*)g_h + cp_off + c * 8192u);
        cpa_commit();
        #pragma unroll
        for (int tl = 0; tl < 4; ++tl) {
            if (tl < 3) {
                const char* src = (const char*)(g_h + (tl + 1) * TILE_FLOATS);
                #pragma unroll
                for (int c = 0; c < 4; ++c)
                    cpa16(buf_s[(tl + 1) & 1] + cp_off + c * 8192u, src + cp_off + c * 8192u);
                cpa_commit();
                cpa_wait<1>();
            } else {
                cpa_wait<0>();
            }
            __syncthreads();
            const int kg = tl * 256 + sub * 64;
            const ulonglong2* wz0 = (const ulonglong2*)(wzr0 + kg);
            const ulonglong2* wz1 = (const ulonglong2*)(wzr1 + kg);
            const ulonglong2* wr0 = (const ulonglong2*)(wrr0 + kg);
            const ulonglong2* wr1 = (const ulonglong2*)(wrr1 + kg);
            const u64* hb = hq[tl & 1];
            #pragma unroll 4
            for (int ii = 0; ii < 16; ++ii) {
                u64 hA = hb[(2 * ii + 0) * 32];
                u64 hB = hb[(2 * ii + 1) * 32];
                ulonglong2 qz0 = wz0[ii], qz1 = wz1[ii], qr0 = wr0[ii], qr1 = wr1[ii];
                ffma2(az0, qz0.x, hA); ffma2(az0, qz0.y, hB);
                ffma2(az1, qz1.x, hA); ffma2(az1, qz1.y, hB);
                ffma2(ar0, qr0.x, hA); ffma2(ar0, qr0.y, hB);
                ffma2(ar1, qr1.x, hA); ffma2(ar1, qr1.y, hB);
            }
            __syncthreads();
        }
        part[(w * 4 + 0) * 32 + lane] = f2sum(az0);
        part[(w * 4 + 1) * 32 + lane] = f2sum(az1);
        part[(w * 4 + 2) * 32 + lane] = f2sum(ar0);
        part[(w * 4 + 3) * 32 + lane] = f2sum(ar1);
        __syncthreads();

        if (w < 8) {
            const int wb = jr >> 1, sl = jr & 1;
            float zsum = 0.f, rsum = 0.f;
            #pragma unroll
            for (int sb = 0; sb < 4; ++sb) {
                int W4 = ((sb << 2) | wb) * 4;
                zsum += part[(W4 + 0 + sl) * 32 + bb];
                rsum += part[(W4 + 2 + sl) * 32 + bb];
            }
            zg = sigmoidf_(zsum + gzv + bzj);
            rg = sigmoidf_(rsum + grv + brj);
            g_u[pidx] = rg * hv;
        }

        grid_bar(2 * t, ncta);

        float ggv = 0.f;
        if (w < 8) ggv = g_gates[2 * plane + gb];

        // ================= phase 2: g, h_new ==============================
        u64 ag0 = 0ull, ag1 = 0ull;
        #pragma unroll
        for (int c = 0; c < 4; ++c)
            cpa16(buf_s[0] + cp_off + c * 8192u, (const char*)g_u + cp_off + c * 8192u);
        cpa_commit();
        #pragma unroll
        for (int tl = 0; tl < 4; ++tl) {
            if (tl < 3) {
                const char* src = (const char*)(g_u + (tl + 1) * TILE_FLOATS);
                #pragma unroll
                for (int c = 0; c < 4; ++c)
                    cpa16(buf_s[(tl + 1) & 1] + cp_off + c * 8192u, src + cp_off + c * 8192u);
                cpa_commit();
                cpa_wait<1>();
            } else {
                cpa_wait<0>();
            }
            __syncthreads();
            const int kg = tl * 256 + sub * 64;
            const ulonglong2* wg0 = (const ulonglong2*)(wgr0 + kg);
            const ulonglong2* wg1 = (const ulonglong2*)(wgr1 + kg);
            const u64* hb = hq[tl & 1];
            #pragma unroll 4
            for (int ii = 0; ii < 16; ++ii) {
                u64 hA = hb[(2 * ii + 0) * 32];
                u64 hB = hb[(2 * ii + 1) * 32];
                ulonglong2 q0 = wg0[ii], q1 = wg1[ii];
                ffma2(ag0, q0.x, hA); ffma2(ag0, q0.y, hB);
                ffma2(ag1, q1.x, hA); ffma2(ag1, q1.y, hB);
            }
            __syncthreads();
        }
        part[(w * 4 + 0) * 32 + lane] = f2sum(ag0);
        part[(w * 4 + 1) * 32 + lane] = f2sum(ag1);
        __syncthreads();

        if (w < 8) {
            const int wb = jr >> 1, sl = jr & 1;
            float gsum = 0.f;
            #pragma unroll
            for (int sb = 0; sb < 4; ++sb) {
                int W4 = ((sb << 2) | wb) * 4;
                gsum += part[(W4 + sl) * 32 + bb];
            }
            float gv = tanhf(gsum + ggv + bgj);
            float hn = zg * hv + (1.0f - zg) * gv;
            g_h[pidx] = hn;
            g_seq[gb] = hn;
            if (t == Sz - 1) hid_out[bb * (2 * Hz) + layer * Hz + jg] = hn;
        }

        grid_bar(2 * t + 1, ncta);
    }
}

// ---------------------------------------------------------------------------
// projY: y[b][s][o] = sum_h seq[s][h][b] * Wy[o][h] + by[o]
// ---------------------------------------------------------------------------
__global__ void __launch_bounds__(TPB) projy_kernel(
    const float* __restrict__ Wy, const float* __restrict__ by, float* __restrict__ y)
{
    __shared__ float xs[256 * 33];
    const int s = blockIdx.x;
    const int tid = threadIdx.x, lane = tid & 31, w = tid >> 5;

    float acc[16];
    #pragma unroll
    for (int q = 0; q < 16; ++q) acc[q] = 0.f;

    for (int kt = 0; kt < 4; ++kt) {
        __syncthreads();
        #pragma unroll
        for (int rep = 0; rep < 32; ++rep) {
            int e = rep * 256 + tid;
            int i = e >> 5, b = e & 31;
            xs[i * 33 + b] = g_seq[((size_t)s * Hz + kt * 256 + i) * Bz + b];
        }
        __syncthreads();
        #pragma unroll
        for (int c = 0; c < 4; ++c) {
            int o = w * 16 + c * 4;
            const float4* w0 = (const float4*)(Wy + (size_t)(o + 0) * Hz + kt * 256);
            const float4* w1 = (const float4*)(Wy + (size_t)(o + 1) * Hz + kt * 256);
            const float4* w2 = (const float4*)(Wy + (size_t)(o + 2) * Hz + kt * 256);
            const float4* w3 = (const float4*)(Wy + (size_t)(o + 3) * Hz + kt * 256);
            float a0 = acc[c * 4 + 0], a1 = acc[c * 4 + 1];
            float a2 = acc[c * 4 + 2], a3 = acc[c * 4 + 3];
            #pragma unroll 8
            for (int i4 = 0; i4 < 64; ++i4) {
                float h0v = xs[(i4 * 4 + 0) * 33 + lane];
                float h1v = xs[(i4 * 4 + 1) * 33 + lane];
                float h2v = xs[(i4 * 4 + 2) * 33 + lane];
                float h3v = xs[(i4 * 4 + 3) * 33 + lane];
                float4 q0 = w0[i4], q1 = w1[i4], q2 = w2[i4], q3 = w3[i4];
                a0 = fmaf(q0.x, h0v, a0); a0 = fmaf(q0.y, h1v, a0); a0 = fmaf(q0.z, h2v, a0); a0 = fmaf(q0.w, h3v, a0);
                a1 = fmaf(q1.x, h0v, a1); a1 = fmaf(q1.y, h1v, a1); a1 = fmaf(q1.z, h2v, a1); a1 = fmaf(q1.w, h3v, a1);
                a2 = fmaf(q2.x, h0v, a2); a2 = fmaf(q2.y, h1v, a2); a2 = fmaf(q2.z, h2v, a2); a2 = fmaf(q2.w, h3v, a2);
                a3 = fmaf(q3.x, h0v, a3); a3 = fmaf(q3.y, h1v, a3); a3 = fmaf(q3.z, h2v, a3); a3 = fmaf(q3.w, h3v, a3);
            }
            acc[c * 4 + 0] = a0; acc[c * 4 + 1] = a1;
            acc[c * 4 + 2] = a2; acc[c * 4 + 3] = a3;
        }
    }
    #pragma unroll
    for (int c = 0; c < 4; ++c) {
        #pragma unroll
        for (int q = 0; q < 4; ++q) {
            int o = w * 16 + c * 4 + q;
            y[(size_t)lane * (Sz * Oz) + (size_t)s * Oz + o] = acc[c * 4 + q] + by[o];
        }
    }
}

// ---------------------------------------------------------------------------
extern "C" void kernel_launch(void* const* d_in, const int* in_sizes, int n_in,
                              void* d_out, int out_size) {
    (void)in_sizes; (void)n_in; (void)out_size;
    const float* x    = (const float*)d_in[0];
    const float* h0   = (const float*)d_in[1];
    const float* Wxz0 = (const float*)d_in[2];
    const float* Whz0 = (const float*)d_in[3];
    const float* bz0  = (const float*)d_in[4];
    const float* Wxr0 = (const float*)d_in[5];
    const float* Whr0 = (const float*)d_in[6];
    const float* br0  = (const float*)d_in[7];
    const float* Wxg0 = (const float*)d_in[8];
    const float* Whg0 = (const float*)d_in[9];
    const float* bg0  = (const float*)d_in[10];
    const float* Wxz1 = (const float*)d_in[11];
    const float* Whz1 = (const float*)d_in[12];
    const float* bz1  = (const float*)d_in[13];
    const float* Wxr1 = (const float*)d_in[14];
    const float* Whr1 = (const float*)d_in[15];
    const float* br1  = (const float*)d_in[16];
    const float* Wxg1 = (const float*)d_in[17];
    const float* Whg1 = (const float*)d_in[18];
    const float* bg1  = (const float*)d_in[19];
    const float* Wy   = (const float*)d_in[20];
    const float* by   = (const float*)d_in[21];

    float* y   = (float*)d_out;
    float* hid = (float*)d_out + (size_t)Bz * Sz * Oz;

    const int scan_smem = SCAN_SMEM_FLOATS * (int)sizeof(float);
    cudaFuncSetAttribute(scan_kernel, cudaFuncAttributeMaxDynamicSharedMemorySize, scan_smem);

    // Layer 0
    proj0_kernel<<<Sz, TPB>>>(x, Wxz0, Wxr0, Wxg0);
    prep_kernel<<<SCAN_GRID, TPB>>>(h0, 0);
    scan_kernel<<<SCAN_GRID, TPBS, scan_smem>>>(Whz0, Whr0, Whg0, bz0, br0, bg0, hid, 0);

    // Layer 1
    proj1_kernel<<<dim3(8, Sz), TPB>>>(Wxz1, Wxr1, Wxg1);
    prep_kernel<<<SCAN_GRID, TPB>>>(h0, 1);
    scan_kernel<<<SCAN_GRID, TPBS, scan_smem>>>(Whz1, Whr1, Whg1, bz1, br1, bg1, hid, 1);

    // Output head
    projy_kernel<<<Sz, TPB>>>(Wy, by, y);
}

// round 6
// speedup vs baseline: 2.2897x; 1.0737x over previous
#include <cuda_runtime.h>
#include <math.h>

// Problem sizes
#define Bz 32
#define Sz 512
#define Iz 128
#define Hz 1024
#define Oz 128
#define TPB 256
#define TPBS 512
#define SCAN_GRID 128

typedef unsigned long long u64;

// Scratch (device globals)
__device__ __align__(16) float g_gates[(size_t)3 * Sz * Hz * Bz];   // [gate][t][j][b]
__device__ __align__(16) float g_seq[(size_t)Sz * Hz * Bz];         // [t][j][b]
__device__ __align__(16) float g_h[Hz * Bz];   // paired: [j/2][b][2] -> (j/2)*64 + 2b + (j&1)
__device__ __align__(16) float g_u[Hz * Bz];   // paired, same as g_h
__device__ int   g_bar[2 * Sz];
__device__ int   g_flag[2 * Sz];

__device__ __forceinline__ float sigmoidf_(float x) {
    return 1.0f / (1.0f + expf(-x));
}

// packed fp32x2 FMA: acc = a * b + acc
__device__ __forceinline__ void ffma2(u64& acc, u64 a, u64 b) {
    asm("fma.rn.f32x2 %0, %1, %2, %0;" : "+l"(acc) : "l"(a), "l"(b));
}
__device__ __forceinline__ float f2sum(u64 v) {
    float lo, hi;
    asm("mov.b64 {%0, %1}, %2;" : "=f"(lo), "=f"(hi) : "l"(v));
    return lo + hi;
}

// cp.async 16B, L1-bypass (.cg)
__device__ __forceinline__ void cpa16(unsigned s, const void* g) {
    asm volatile("cp.async.cg.shared.global [%0], [%1], 16;" :: "r"(s), "l"(g));
}
__device__ __forceinline__ void cpa_commit() {
    asm volatile("cp.async.commit_group;" ::: "memory");
}
template <int N>
__device__ __forceinline__ void cpa_wait() {
    asm volatile("cp.async.wait_group %0;" :: "n"(N) : "memory");
}

// Fence-free grid barrier: release-atomic arrive, single-writer release flag,
// acquire spin. All cross-CTA data reads bypass L1 (cp.async.cg).
__device__ __forceinline__ void grid_bar(int i, int ncta) {
    __syncthreads();
    if (threadIdx.x == 0) {
        int v;
        asm volatile("atom.release.gpu.global.add.s32 %0, [%1], 1;"
                     : "=r"(v) : "l"(&g_bar[i]) : "memory");
        if (v == ncta - 1) {
            asm volatile("st.release.gpu.global.s32 [%0], 1;"
                         :: "l"(&g_flag[i]) : "memory");
        } else {
            int f;
            do {
                asm volatile("ld.acquire.gpu.global.s32 %0, [%1];"
                             : "=r"(f) : "l"(&g_flag[i]) : "memory");
            } while (f == 0);
        }
    }
    __syncthreads();
}

// ---------------------------------------------------------------------------
// prep: init h state (paired layout) + zero barrier counters/flags
// ---------------------------------------------------------------------------
__global__ void prep_kernel(const float* __restrict__ h0, int layer) {
    int idx = blockIdx.x * TPB + threadIdx.x;
    int j = idx >> 5;
    int b = idx & 31;
    g_h[(j >> 1) * 64 + 2 * b + (j & 1)] = h0[b * (2 * Hz) + layer * Hz + j];
    if (idx < 2 * Sz) { g_bar[idx] = 0; g_flag[idx] = 0; }
}

// ---------------------------------------------------------------------------
// proj0: layer-0 input projections (K=128)
// ---------------------------------------------------------------------------
__global__ void __launch_bounds__(TPB) proj0_kernel(
    const float* __restrict__ x,
    const float* __restrict__ Wz, const float* __restrict__ Wr, const float* __restrict__ Wg)
{
    __shared__ float xs[Iz * 33];
    const int s = blockIdx.x;
    const int tid = threadIdx.x, lane = tid & 31, w = tid >> 5;

    #pragma unroll
    for (int rep = 0; rep < 16; ++rep) {
        int e = rep * 256 + tid;
        int b = e >> 7, i = e & 127;
        xs[i * 33 + b] = x[((size_t)b * Sz + s) * Iz + i];
    }
    __syncthreads();

    for (int c = 0; c < 96; ++c) {
        int rr = w * 384 + c * 4;
        int g = rr >> 10;
        int j = rr & 1023;
        const float* Wp = (g == 0) ? Wz : ((g == 1) ? Wr : Wg);
        const float4* w0 = (const float4*)(Wp + (size_t)(j + 0) * Iz);
        const float4* w1 = (const float4*)(Wp + (size_t)(j + 1) * Iz);
        const float4* w2 = (const float4*)(Wp + (size_t)(j + 2) * Iz);
        const float4* w3 = (const float4*)(Wp + (size_t)(j + 3) * Iz);
        float a0 = 0.f, a1 = 0.f, a2 = 0.f, a3 = 0.f;
        #pragma unroll 8
        for (int i4 = 0; i4 < 32; ++i4) {
            float h0v = xs[(i4 * 4 + 0) * 33 + lane];
            float h1v = xs[(i4 * 4 + 1) * 33 + lane];
            float h2v = xs[(i4 * 4 + 2) * 33 + lane];
            float h3v = xs[(i4 * 4 + 3) * 33 + lane];
            float4 q0 = w0[i4], q1 = w1[i4], q2 = w2[i4], q3 = w3[i4];
            a0 = fmaf(q0.x, h0v, a0); a0 = fmaf(q0.y, h1v, a0); a0 = fmaf(q0.z, h2v, a0); a0 = fmaf(q0.w, h3v, a0);
            a1 = fmaf(q1.x, h0v, a1); a1 = fmaf(q1.y, h1v, a1); a1 = fmaf(q1.z, h2v, a1); a1 = fmaf(q1.w, h3v, a1);
            a2 = fmaf(q2.x, h0v, a2); a2 = fmaf(q2.y, h1v, a2); a2 = fmaf(q2.z, h2v, a2); a2 = fmaf(q2.w, h3v, a2);
            a3 = fmaf(q3.x, h0v, a3); a3 = fmaf(q3.y, h1v, a3); a3 = fmaf(q3.z, h2v, a3); a3 = fmaf(q3.w, h3v, a3);
        }
        size_t base = (((size_t)g * Sz + s) * Hz + j) * Bz + lane;
        g_gates[base +  0] = a0;
        g_gates[base + 32] = a1;
        g_gates[base + 64] = a2;
        g_gates[base + 96] = a3;
    }
}

// ---------------------------------------------------------------------------
// proj1: layer-1 input projections (K=1024) from g_seq
// ---------------------------------------------------------------------------
__global__ void __launch_bounds__(TPB) proj1_kernel(
    const float* __restrict__ Wz, const float* __restrict__ Wr, const float* __restrict__ Wg)
{
    __shared__ float xs[256 * 33];
    const int s = blockIdx.y;
    const int rb = blockIdx.x;
    const int tid = threadIdx.x, lane = tid & 31, w = tid >> 5;

    float acc[48];
    #pragma unroll
    for (int q = 0; q < 48; ++q) acc[q] = 0.f;

    for (int kt = 0; kt < 4; ++kt) {
        __syncthreads();
        #pragma unroll
        for (int rep = 0; rep < 32; ++rep) {
            int e = rep * 256 + tid;
            int i = e >> 5, b = e & 31;
            xs[i * 33 + b] = g_seq[((size_t)s * Hz + kt * 256 + i) * Bz + b];
        }
        __syncthreads();
        #pragma unroll
        for (int c = 0; c < 12; ++c) {
            int rr = rb * 384 + w * 48 + c * 4;
            int g = rr >> 10, j = rr & 1023;
            const float* Wp = (g == 0) ? Wz : ((g == 1) ? Wr : Wg);
            const float4* w0 = (const float4*)(Wp + (size_t)(j + 0) * Hz + kt * 256);
            const float4* w1 = (const float4*)(Wp + (size_t)(j + 1) * Hz + kt * 256);
            const float4* w2 = (const float4*)(Wp + (size_t)(j + 2) * Hz + kt * 256);
            const float4* w3 = (const float4*)(Wp + (size_t)(j + 3) * Hz + kt * 256);
            float a0 = acc[c * 4 + 0], a1 = acc[c * 4 + 1];
            float a2 = acc[c * 4 + 2], a3 = acc[c * 4 + 3];
            #pragma unroll 8
            for (int i4 = 0; i4 < 64; ++i4) {
                float h0v = xs[(i4 * 4 + 0) * 33 + lane];
                float h1v = xs[(i4 * 4 + 1) * 33 + lane];
                float h2v = xs[(i4 * 4 + 2) * 33 + lane];
                float h3v = xs[(i4 * 4 + 3) * 33 + lane];
                float4 q0 = w0[i4], q1 = w1[i4], q2 = w2[i4], q3 = w3[i4];
                a0 = fmaf(q0.x, h0v, a0); a0 = fmaf(q0.y, h1v, a0); a0 = fmaf(q0.z, h2v, a0); a0 = fmaf(q0.w, h3v, a0);
                a1 = fmaf(q1.x, h0v, a1); a1 = fmaf(q1.y, h1v, a1); a1 = fmaf(q1.z, h2v, a1); a1 = fmaf(q1.w, h3v, a1);
                a2 = fmaf(q2.x, h0v, a2); a2 = fmaf(q2.y, h1v, a2); a2 = fmaf(q2.z, h2v, a2); a2 = fmaf(q2.w, h3v, a2);
                a3 = fmaf(q3.x, h0v, a3); a3 = fmaf(q3.y, h1v, a3); a3 = fmaf(q3.z, h2v, a3); a3 = fmaf(q3.w, h3v, a3);
            }
            acc[c * 4 + 0] = a0; acc[c * 4 + 1] = a1;
            acc[c * 4 + 2] = a2; acc[c * 4 + 3] = a3;
        }
    }
    #pragma unroll
    for (int c = 0; c < 12; ++c) {
        int rr = rb * 384 + w * 48 + c * 4;
        int g = rr >> 10, j = rr & 1023;
        size_t base = (((size_t)g * Sz + s) * Hz + j) * Bz + lane;
        g_gates[base +  0] = acc[c * 4 + 0];
        g_gates[base + 32] = acc[c * 4 + 1];
        g_gates[base + 64] = acc[c * 4 + 2];
        g_gates[base + 96] = acc[c * 4 + 3];
    }
}

// ---------------------------------------------------------------------------
// scan v6: high-reuse warp mapping.
//   phase1: warp (half=w&1, sub=w>>1): 4 j x {z,r} = 8 accs, k-slice 32/tile
//           -> each h load feeds 8 ffma2
//   phase2: warp sub2=w: all 8 g rows = 8 accs, k-slice 16/tile
//           -> each h load feeds 8 ffma2, single h pass
// Double-buffered cp.async.cg staging (4 tiles x 32KB per phase),
// fence-free grid barrier, packed fp32x2 FFMA. 128 CTAs x 512 threads.
//
// SMEM (floats): buf0 8192 | buf1 8192 | ws 24576 | part 4096 = 45056 (176KB)
// ---------------------------------------------------------------------------
#define SCAN_SMEM_FLOATS (8192 + 8192 + 24576 + 4096)
#define TILE_FLOATS 8192   // 128 k-pairs x [b][2] = 32KB

__global__ void __launch_bounds__(TPBS, 1) scan_kernel(
    const float* __restrict__ Whz, const float* __restrict__ Whr, const float* __restrict__ Whg,
    const float* __restrict__ bz,  const float* __restrict__ br,  const float* __restrict__ bg,
    float* __restrict__ hid_out, int layer)
{
    extern __shared__ float smem[];
    float* bufs = smem;                    // 2 x 8192
    float* ws   = smem + 2 * TILE_FLOATS;  // 24576  (z:0-7, r:8-15, g:16-23)
    float* part = ws + 24576;              // [16 warps][8][32]

    const int tid = threadIdx.x, lane = tid & 31, w = tid >> 5;
    const int jbase = blockIdx.x * 8;
    const int ncta = (int)gridDim.x;

    unsigned sbase;
    asm("{.reg .u64 t; cvta.to.shared.u64 t, %1; cvt.u32.u64 %0, t;}"
        : "=r"(sbase) : "l"(smem));
    const unsigned buf_s[2] = { sbase, sbase + TILE_FLOATS * 4u };
    const unsigned cp_off = (unsigned)tid * 16u;

    // ---- preload weights (once per layer): 6144 float4 --------------------
    for (int idx = tid; idx < 6144; idx += TPBS) {
        int g  = idx >> 11;
        int r2 = idx & 2047;
        int jl = r2 >> 8;
        int k4 = r2 & 255;
        const float* W = (g == 0) ? Whz : ((g == 1) ? Whr : Whg);
        float4 v = *(const float4*)(W + (size_t)(jbase + jl) * Hz + k4 * 4);
        *(float4*)&ws[((g * 8 + jl) << 10) + k4 * 4] = v;
    }
    __syncthreads();

    // reduction identity (warps 0..7): thread owns (jr, bb)
    const int jr = w & 7;
    const int jg = jbase + jr;
    const int bb = lane;
    const float bzj = bz[jg], brj = br[jg], bgj = bg[jg];
    const size_t plane = (size_t)Sz * Hz * Bz;
    const int pidx = (jg >> 1) * 64 + 2 * bb + (jg & 1);

    // phase-1 mapping: half = w&1 (j rows half*4..half*4+3), sub = w>>1 (k-slice)
    const int half = w & 1, sub = w >> 1;
    const float* wz_[4], * wr_[4], * wg_[8];
    #pragma unroll
    for (int q = 0; q < 4; ++q) {
        wz_[q] = &ws[(0 + half * 4 + q) * 1024];
        wr_[q] = &ws[(8 + half * 4 + q) * 1024];
    }
    #pragma unroll
    for (int q = 0; q < 8; ++q) wg_[q] = &ws[(16 + q) * 1024];

    // h pointers (u64, lane-indexed) into each buffer
    const u64* hq1[2] = {
        (const u64*)&bufs[(sub * 16) * 64 + 2 * lane],
        (const u64*)&bufs[TILE_FLOATS + (sub * 16) * 64 + 2 * lane]
    };
    const u64* hq2[2] = {
        (const u64*)&bufs[(w * 8) * 64 + 2 * lane],
        (const u64*)&bufs[TILE_FLOATS + (w * 8) * 64 + 2 * lane]
    };

    for (int t = 0; t < Sz; ++t) {
        const size_t gb = ((size_t)t * Hz + jg) * Bz + bb;
        float gzv = 0.f, grv = 0.f, hv = 0.f, zg = 0.f, rg = 0.f;
        if (w < 8) {
            gzv = g_gates[gb];
            grv = g_gates[plane + gb];
            hv  = g_h[pidx];
        }

        // ================= phase 1: z, r, u = r*h =========================
        u64 az[4] = {0,0,0,0}, ar[4] = {0,0,0,0};
        #pragma unroll
        for (int c = 0; c < 4; ++c)
            cpa16(buf_s[0] + cp_off + c * 8192u, (const char*)g_h + cp_off + c * 8192u);
        cpa_commit();
        #pragma unroll
        for (int tl = 0; tl < 4; ++tl) {
            if (tl < 3) {
                const char* src = (const char*)(g_h + (tl + 1) * TILE_FLOATS);
                #pragma unroll
                for (int c = 0; c < 4; ++c)
                    cpa16(buf_s[(tl + 1) & 1] + cp_off + c * 8192u, src + cp_off + c * 8192u);
                cpa_commit();
                cpa_wait<1>();
            } else {
                cpa_wait<0>();
            }
            __syncthreads();
            const int kg = tl * 256 + sub * 32;   // global k offset of this warp's slice
            const u64* hb = hq1[tl & 1];
            #pragma unroll
            for (int ii = 0; ii < 8; ++ii) {
                u64 hA = hb[(2 * ii + 0) * 32];
                u64 hB = hb[(2 * ii + 1) * 32];
                #pragma unroll
                for (int q = 0; q < 4; ++q) {
                    ulonglong2 qz = ((const ulonglong2*)(wz_[q] + kg))[ii];
                    ulonglong2 qr = ((const ulonglong2*)(wr_[q] + kg))[ii];
                    ffma2(az[q], qz.x, hA); ffma2(az[q], qz.y, hB);
                    ffma2(ar[q], qr.x, hA); ffma2(ar[q], qr.y, hB);
                }
            }
            __syncthreads();
        }
        #pragma unroll
        for (int q = 0; q < 4; ++q) {
            part[(w * 8 + q) * 32 + lane]     = f2sum(az[q]);
            part[(w * 8 + 4 + q) * 32 + lane] = f2sum(ar[q]);
        }
        __syncthreads();

        if (w < 8) {
            const int rh = jr >> 2, jl = jr & 3;
            float zsum = 0.f, rsum = 0.f;
            #pragma unroll
            for (int sb = 0; sb < 8; ++sb) {
                int wi = sb * 2 + rh;
                zsum += part[(wi * 8 + jl) * 32 + bb];
                rsum += part[(wi * 8 + 4 + jl) * 32 + bb];
            }
            zg = sigmoidf_(zsum + gzv + bzj);
            rg = sigmoidf_(rsum + grv + brj);
            g_u[pidx] = rg * hv;
        }

        grid_bar(2 * t, ncta);

        float ggv = 0.f;
        if (w < 8) ggv = g_gates[2 * plane + gb];

        // ================= phase 2: g, h_new ==============================
        u64 ag[8] = {0,0,0,0,0,0,0,0};
        #pragma unroll
        for (int c = 0; c < 4; ++c)
            cpa16(buf_s[0] + cp_off + c * 8192u, (const char*)g_u + cp_off + c * 8192u);
        cpa_commit();
        #pragma unroll
        for (int tl = 0; tl < 4; ++tl) {
            if (tl < 3) {
                const char* src = (const char*)(g_u + (tl + 1) * TILE_FLOATS);
                #pragma unroll
                for (int c = 0; c < 4; ++c)
                    cpa16(buf_s[(tl + 1) & 1] + cp_off + c * 8192u, src + cp_off + c * 8192u);
                cpa_commit();
                cpa_wait<1>();
            } else {
                cpa_wait<0>();
            }
            __syncthreads();
            const int kg = tl * 256 + w * 16;     // this warp's 16-k slice
            const u64* hb = hq2[tl & 1];
            #pragma unroll
            for (int ii = 0; ii < 4; ++ii) {
                u64 hA = hb[(2 * ii + 0) * 32];
                u64 hB = hb[(2 * ii + 1) * 32];
                #pragma unroll
                for (int q = 0; q < 8; ++q) {
                    ulonglong2 qg = ((const ulonglong2*)(wg_[q] + kg))[ii];
                    ffma2(ag[q], qg.x, hA); ffma2(ag[q], qg.y, hB);
                }
            }
            __syncthreads();
        }
        #pragma unroll
        for (int q = 0; q < 8; ++q)
            part[(w * 8 + q) * 32 + lane] = f2sum(ag[q]);
        __syncthreads();

        if (w < 8) {
            float gsum = 0.f;
            #pragma unroll
            for (int sb = 0; sb < 16; ++sb)
                gsum += part[(sb * 8 + jr) * 32 + bb];
            float gv = tanhf(gsum + ggv + bgj);
            float hn = zg * hv + (1.0f - zg) * gv;
            g_h[pidx] = hn;
            g_seq[gb] = hn;
            if (t == Sz - 1) hid_out[bb * (2 * Hz) + layer * Hz + jg] = hn;
        }

        grid_bar(2 * t + 1, ncta);
    }
}

// ---------------------------------------------------------------------------
// projY: y[b][s][o] = sum_h seq[s][h][b] * Wy[o][h] + by[o]
// ---------------------------------------------------------------------------
__global__ void __launch_bounds__(TPB) projy_kernel(
    const float* __restrict__ Wy, const float* __restrict__ by, float* __restrict__ y)
{
    __shared__ float xs[256 * 33];
    const int s = blockIdx.x;
    const int tid = threadIdx.x, lane = tid & 31, w = tid >> 5;

    float acc[16];
    #pragma unroll
    for (int q = 0; q < 16; ++q) acc[q] = 0.f;

    for (int kt = 0; kt < 4; ++kt) {
        __syncthreads();
        #pragma unroll
        for (int rep = 0; rep < 32; ++rep) {
            int e = rep * 256 + tid;
            int i = e >> 5, b = e & 31;
            xs[i * 33 + b] = g_seq[((size_t)s * Hz + kt * 256 + i) * Bz + b];
        }
        __syncthreads();
        #pragma unroll
        for (int c = 0; c < 4; ++c) {
            int o = w * 16 + c * 4;
            const float4* w0 = (const float4*)(Wy + (size_t)(o + 0) * Hz + kt * 256);
            const float4* w1 = (const float4*)(Wy + (size_t)(o + 1) * Hz + kt * 256);
            const float4* w2 = (const float4*)(Wy + (size_t)(o + 2) * Hz + kt * 256);
            const float4* w3 = (const float4*)(Wy + (size_t)(o + 3) * Hz + kt * 256);
            float a0 = acc[c * 4 + 0], a1 = acc[c * 4 + 1];
            float a2 = acc[c * 4 + 2], a3 = acc[c * 4 + 3];
            #pragma unroll 8
            for (int i4 = 0; i4 < 64; ++i4) {
                float h0v = xs[(i4 * 4 + 0) * 33 + lane];
                float h1v = xs[(i4 * 4 + 1) * 33 + lane];
                float h2v = xs[(i4 * 4 + 2) * 33 + lane];
                float h3v = xs[(i4 * 4 + 3) * 33 + lane];
                float4 q0 = w0[i4], q1 = w1[i4], q2 = w2[i4], q3 = w3[i4];
                a0 = fmaf(q0.x, h0v, a0); a0 = fmaf(q0.y, h1v, a0); a0 = fmaf(q0.z, h2v, a0); a0 = fmaf(q0.w, h3v, a0);
                a1 = fmaf(q1.x, h0v, a1); a1 = fmaf(q1.y, h1v, a1); a1 = fmaf(q1.z, h2v, a1); a1 = fmaf(q1.w, h3v, a1);
                a2 = fmaf(q2.x, h0v, a2); a2 = fmaf(q2.y, h1v, a2); a2 = fmaf(q2.z, h2v, a2); a2 = fmaf(q2.w, h3v, a2);
                a3 = fmaf(q3.x, h0v, a3); a3 = fmaf(q3.y, h1v, a3); a3 = fmaf(q3.z, h2v, a3); a3 = fmaf(q3.w, h3v, a3);
            }
            acc[c * 4 + 0] = a0; acc[c * 4 + 1] = a1;
            acc[c * 4 + 2] = a2; acc[c * 4 + 3] = a3;
        }
    }
    #pragma unroll
    for (int c = 0; c < 4; ++c) {
        #pragma unroll
        for (int q = 0; q < 4; ++q) {
            int o = w * 16 + c * 4 + q;
            y[(size_t)lane * (Sz * Oz) + (size_t)s * Oz + o] = acc[c * 4 + q] + by[o];
        }
    }
}

// ---------------------------------------------------------------------------
extern "C" void kernel_launch(void* const* d_in, const int* in_sizes, int n_in,
                              void* d_out, int out_size) {
    (void)in_sizes; (void)n_in; (void)out_size;
    const float* x    = (const float*)d_in[0];
    const float* h0   = (const float*)d_in[1];
    const float* Wxz0 = (const float*)d_in[2];
    const float* Whz0 = (const float*)d_in[3];
    const float* bz0  = (const float*)d_in[4];
    const float* Wxr0 = (const float*)d_in[5];
    const float* Whr0 = (const float*)d_in[6];
    const float* br0  = (const float*)d_in[7];
    const float* Wxg0 = (const float*)d_in[8];
    const float* Whg0 = (const float*)d_in[9];
    const float* bg0  = (const float*)d_in[10];
    const float* Wxz1 = (const float*)d_in[11];
    const float* Whz1 = (const float*)d_in[12];
    const float* bz1  = (const float*)d_in[13];
    const float* Wxr1 = (const float*)d_in[14];
    const float* Whr1 = (const float*)d_in[15];
    const float* br1  = (const float*)d_in[16];
    const float* Wxg1 = (const float*)d_in[17];
    const float* Whg1 = (const float*)d_in[18];
    const float* bg1  = (const float*)d_in[19];
    const float* Wy   = (const float*)d_in[20];
    const float* by   = (const float*)d_in[21];

    float* y   = (float*)d_out;
    float* hid = (float*)d_out + (size_t)Bz * Sz * Oz;

    const int scan_smem = SCAN_SMEM_FLOATS * (int)sizeof(float);
    cudaFuncSetAttribute(scan_kernel, cudaFuncAttributeMaxDynamicSharedMemorySize, scan_smem);

    // Layer 0
    proj0_kernel<<<Sz, TPB>>>(x, Wxz0, Wxr0, Wxg0);
    prep_kernel<<<SCAN_GRID, TPB>>>(h0, 0);
    scan_kernel<<<SCAN_GRID, TPBS, scan_smem>>>(Whz0, Whr0, Whg0, bz0, br0, bg0, hid, 0);

    // Layer 1
    proj1_kernel<<<dim3(8, Sz), TPB>>>(Wxz1, Wxr1, Wxg1);
    prep_kernel<<<SCAN_GRID, TPB>>>(h0, 1);
    scan_kernel<<<SCAN_GRID, TPBS, scan_smem>>>(Whz1, Whr1, Whg1, bz1, br1, bg1, hid, 1);

    // Output head
    projy_kernel<<<Sz, TPB>>>(Wy, by, y);
}

// round 7
// speedup vs baseline: 2.4041x; 1.0500x over previous
#include <cuda_runtime.h>
#include <math.h>

// Problem sizes
#define Bz 32
#define Sz 512
#define Iz 128
#define Hz 1024
#define Oz 128
#define TPB 256
#define TPBS 512
#define SCAN_GRID 128

typedef unsigned long long u64;

// Scratch (device globals)
__device__ __align__(16) float g_gates[(size_t)3 * Sz * Hz * Bz];   // [gate][t][j][b]
__device__ __align__(16) float g_seq[(size_t)Sz * Hz * Bz];         // [t][j][b]
__device__ __align__(16) float g_h[Hz * Bz];   // paired: [j/2][b][2] -> (j/2)*64 + 2b + (j&1)
__device__ __align__(16) float g_u[Hz * Bz];   // paired, same as g_h
__device__ int   g_bar[2 * Sz];
__device__ int   g_flag[2 * Sz];

__device__ __forceinline__ float sigmoidf_(float x) {
    return 1.0f / (1.0f + expf(-x));
}

// packed fp32x2 FMA: acc = a * b + acc
__device__ __forceinline__ void ffma2(u64& acc, u64 a, u64 b) {
    asm("fma.rn.f32x2 %0, %1, %2, %0;" : "+l"(acc) : "l"(a), "l"(b));
}
__device__ __forceinline__ float f2sum(u64 v) {
    float lo, hi;
    asm("mov.b64 {%0, %1}, %2;" : "=f"(lo), "=f"(hi) : "l"(v));
    return lo + hi;
}

// cp.async 16B, L1-bypass (.cg)
__device__ __forceinline__ void cpa16(unsigned s, const void* g) {
    asm volatile("cp.async.cg.shared.global [%0], [%1], 16;" :: "r"(s), "l"(g));
}
__device__ __forceinline__ void cpa_commit() {
    asm volatile("cp.async.commit_group;" ::: "memory");
}
template <int N>
__device__ __forceinline__ void cpa_wait() {
    asm volatile("cp.async.wait_group %0;" :: "n"(N) : "memory");
}

// Fence-free grid barrier: release-atomic arrive, single-writer release flag,
// acquire spin. All cross-CTA data reads bypass L1 (cp.async.cg).
__device__ __forceinline__ void grid_bar(int i, int ncta) {
    __syncthreads();
    if (threadIdx.x == 0) {
        int v;
        asm volatile("atom.release.gpu.global.add.s32 %0, [%1], 1;"
                     : "=r"(v) : "l"(&g_bar[i]) : "memory");
        if (v == ncta - 1) {
            asm volatile("st.release.gpu.global.s32 [%0], 1;"
                         :: "l"(&g_flag[i]) : "memory");
        } else {
            int f;
            do {
                asm volatile("ld.acquire.gpu.global.s32 %0, [%1];"
                             : "=r"(f) : "l"(&g_flag[i]) : "memory");
            } while (f == 0);
        }
    }
    __syncthreads();
}

// ---------------------------------------------------------------------------
// prep: init h state (paired layout) + zero barrier counters/flags
// ---------------------------------------------------------------------------
__global__ void prep_kernel(const float* __restrict__ h0, int layer) {
    int idx = blockIdx.x * TPB + threadIdx.x;
    int j = idx >> 5;
    int b = idx & 31;
    g_h[(j >> 1) * 64 + 2 * b + (j & 1)] = h0[b * (2 * Hz) + layer * Hz + j];
    if (idx < 2 * Sz) { g_bar[idx] = 0; g_flag[idx] = 0; }
}

// ---------------------------------------------------------------------------
// proj0: layer-0 input projections (K=128)
// ---------------------------------------------------------------------------
__global__ void __launch_bounds__(TPB) proj0_kernel(
    const float* __restrict__ x,
    const float* __restrict__ Wz, const float* __restrict__ Wr, const float* __restrict__ Wg)
{
    __shared__ float xs[Iz * 33];
    const int s = blockIdx.x;
    const int tid = threadIdx.x, lane = tid & 31, w = tid >> 5;

    #pragma unroll
    for (int rep = 0; rep < 16; ++rep) {
        int e = rep * 256 + tid;
        int b = e >> 7, i = e & 127;
        xs[i * 33 + b] = x[((size_t)b * Sz + s) * Iz + i];
    }
    __syncthreads();

    for (int c = 0; c < 96; ++c) {
        int rr = w * 384 + c * 4;
        int g = rr >> 10;
        int j = rr & 1023;
        const float* Wp = (g == 0) ? Wz : ((g == 1) ? Wr : Wg);
        const float4* w0 = (const float4*)(Wp + (size_t)(j + 0) * Iz);
        const float4* w1 = (const float4*)(Wp + (size_t)(j + 1) * Iz);
        const float4* w2 = (const float4*)(Wp + (size_t)(j + 2) * Iz);
        const float4* w3 = (const float4*)(Wp + (size_t)(j + 3) * Iz);
        float a0 = 0.f, a1 = 0.f, a2 = 0.f, a3 = 0.f;
        #pragma unroll 8
        for (int i4 = 0; i4 < 32; ++i4) {
            float h0v = xs[(i4 * 4 + 0) * 33 + lane];
            float h1v = xs[(i4 * 4 + 1) * 33 + lane];
            float h2v = xs[(i4 * 4 + 2) * 33 + lane];
            float h3v = xs[(i4 * 4 + 3) * 33 + lane];
            float4 q0 = w0[i4], q1 = w1[i4], q2 = w2[i4], q3 = w3[i4];
            a0 = fmaf(q0.x, h0v, a0); a0 = fmaf(q0.y, h1v, a0); a0 = fmaf(q0.z, h2v, a0); a0 = fmaf(q0.w, h3v, a0);
            a1 = fmaf(q1.x, h0v, a1); a1 = fmaf(q1.y, h1v, a1); a1 = fmaf(q1.z, h2v, a1); a1 = fmaf(q1.w, h3v, a1);
            a2 = fmaf(q2.x, h0v, a2); a2 = fmaf(q2.y, h1v, a2); a2 = fmaf(q2.z, h2v, a2); a2 = fmaf(q2.w, h3v, a2);
            a3 = fmaf(q3.x, h0v, a3); a3 = fmaf(q3.y, h1v, a3); a3 = fmaf(q3.z, h2v, a3); a3 = fmaf(q3.w, h3v, a3);
        }
        size_t base = (((size_t)g * Sz + s) * Hz + j) * Bz + lane;
        g_gates[base +  0] = a0;
        g_gates[base + 32] = a1;
        g_gates[base + 64] = a2;
        g_gates[base + 96] = a3;
    }
}

// ---------------------------------------------------------------------------
// proj1: layer-1 input projections (K=1024) from g_seq
// ---------------------------------------------------------------------------
__global__ void __launch_bounds__(TPB) proj1_kernel(
    const float* __restrict__ Wz, const float* __restrict__ Wr, const float* __restrict__ Wg)
{
    __shared__ float xs[256 * 33];
    const int s = blockIdx.y;
    const int rb = blockIdx.x;
    const int tid = threadIdx.x, lane = tid & 31, w = tid >> 5;

    float acc[48];
    #pragma unroll
    for (int q = 0; q < 48; ++q) acc[q] = 0.f;

    for (int kt = 0; kt < 4; ++kt) {
        __syncthreads();
        #pragma unroll
        for (int rep = 0; rep < 32; ++rep) {
            int e = rep * 256 + tid;
            int i = e >> 5, b = e & 31;
            xs[i * 33 + b] = g_seq[((size_t)s * Hz + kt * 256 + i) * Bz + b];
        }
        __syncthreads();
        #pragma unroll
        for (int c = 0; c < 12; ++c) {
            int rr = rb * 384 + w * 48 + c * 4;
            int g = rr >> 10, j = rr & 1023;
            const float* Wp = (g == 0) ? Wz : ((g == 1) ? Wr : Wg);
            const float4* w0 = (const float4*)(Wp + (size_t)(j + 0) * Hz + kt * 256);
            const float4* w1 = (const float4*)(Wp + (size_t)(j + 1) * Hz + kt * 256);
            const float4* w2 = (const float4*)(Wp + (size_t)(j + 2) * Hz + kt * 256);
            const float4* w3 = (const float4*)(Wp + (size_t)(j + 3) * Hz + kt * 256);
            float a0 = acc[c * 4 + 0], a1 = acc[c * 4 + 1];
            float a2 = acc[c * 4 + 2], a3 = acc[c * 4 + 3];
            #pragma unroll 8
            for (int i4 = 0; i4 < 64; ++i4) {
                float h0v = xs[(i4 * 4 + 0) * 33 + lane];
                float h1v = xs[(i4 * 4 + 1) * 33 + lane];
                float h2v = xs[(i4 * 4 + 2) * 33 + lane];
                float h3v = xs[(i4 * 4 + 3) * 33 + lane];
                float4 q0 = w0[i4], q1 = w1[i4], q2 = w2[i4], q3 = w3[i4];
                a0 = fmaf(q0.x, h0v, a0); a0 = fmaf(q0.y, h1v, a0); a0 = fmaf(q0.z, h2v, a0); a0 = fmaf(q0.w, h3v, a0);
                a1 = fmaf(q1.x, h0v, a1); a1 = fmaf(q1.y, h1v, a1); a1 = fmaf(q1.z, h2v, a1); a1 = fmaf(q1.w, h3v, a1);
                a2 = fmaf(q2.x, h0v, a2); a2 = fmaf(q2.y, h1v, a2); a2 = fmaf(q2.z, h2v, a2); a2 = fmaf(q2.w, h3v, a2);
                a3 = fmaf(q3.x, h0v, a3); a3 = fmaf(q3.y, h1v, a3); a3 = fmaf(q3.z, h2v, a3); a3 = fmaf(q3.w, h3v, a3);
            }
            acc[c * 4 + 0] = a0; acc[c * 4 + 1] = a1;
            acc[c * 4 + 2] = a2; acc[c * 4 + 3] = a3;
        }
    }
    #pragma unroll
    for (int c = 0; c < 12; ++c) {
        int rr = rb * 384 + w * 48 + c * 4;
        int g = rr >> 10, j = rr & 1023;
        size_t base = (((size_t)g * Sz + s) * Hz + j) * Bz + lane;
        g_gates[base +  0] = acc[c * 4 + 0];
        g_gates[base + 32] = acc[c * 4 + 1];
        g_gates[base + 64] = acc[c * 4 + 2];
        g_gates[base + 96] = acc[c * 4 + 3];
    }
}

// ---------------------------------------------------------------------------
// scan v6: high-reuse warp mapping.
//   phase1: warp (half=w&1, sub=w>>1): 4 j x {z,r} = 8 accs, k-slice 32/tile
//           -> each h load feeds 8 ffma2
//   phase2: warp sub2=w: all 8 g rows = 8 accs, k-slice 16/tile
//           -> each h load feeds 8 ffma2, single h pass
// Double-buffered cp.async.cg staging (4 tiles x 32KB per phase),
// fence-free grid barrier, packed fp32x2 FFMA. 128 CTAs x 512 threads.
//
// SMEM (floats): buf0 8192 | buf1 8192 | ws 24576 | part 4096 = 45056 (176KB)
// ---------------------------------------------------------------------------
#define SCAN_SMEM_FLOATS (8192 + 8192 + 24576 + 4096)
#define TILE_FLOATS 8192   // 128 k-pairs x [b][2] = 32KB

__global__ void __launch_bounds__(TPBS, 1) scan_kernel(
    const float* __restrict__ Whz, const float* __restrict__ Whr, const float* __restrict__ Whg,
    const float* __restrict__ bz,  const float* __restrict__ br,  const float* __restrict__ bg,
    float* __restrict__ hid_out, int layer)
{
    extern __shared__ float smem[];
    float* bufs = smem;                    // 2 x 8192
    float* ws   = smem + 2 * TILE_FLOATS;  // 24576  (z:0-7, r:8-15, g:16-23)
    float* part = ws + 24576;              // [16 warps][8][32]

    const int tid = threadIdx.x, lane = tid & 31, w = tid >> 5;
    const int jbase = blockIdx.x * 8;
    const int ncta = (int)gridDim.x;

    unsigned sbase;
    asm("{.reg .u64 t; cvta.to.shared.u64 t, %1; cvt.u32.u64 %0, t;}"
        : "=r"(sbase) : "l"(smem));
    const unsigned buf_s[2] = { sbase, sbase + TILE_FLOATS * 4u };
    const unsigned cp_off = (unsigned)tid * 16u;

    // ---- preload weights (once per layer): 6144 float4 --------------------
    for (int idx = tid; idx < 6144; idx += TPBS) {
        int g  = idx >> 11;
        int r2 = idx & 2047;
        int jl = r2 >> 8;
        int k4 = r2 & 255;
        const float* W = (g == 0) ? Whz : ((g == 1) ? Whr : Whg);
        float4 v = *(const float4*)(W + (size_t)(jbase + jl) * Hz + k4 * 4);
        *(float4*)&ws[((g * 8 + jl) << 10) + k4 * 4] = v;
    }
    __syncthreads();

    // reduction identity (warps 0..7): thread owns (jr, bb)
    const int jr = w & 7;
    const int jg = jbase + jr;
    const int bb = lane;
    const float bzj = bz[jg], brj = br[jg], bgj = bg[jg];
    const size_t plane = (size_t)Sz * Hz * Bz;
    const int pidx = (jg >> 1) * 64 + 2 * bb + (jg & 1);

    // phase-1 mapping: half = w&1 (j rows half*4..half*4+3), sub = w>>1 (k-slice)
    const int half = w & 1, sub = w >> 1;
    const float* wz_[4], * wr_[4], * wg_[8];
    #pragma unroll
    for (int q = 0; q < 4; ++q) {
        wz_[q] = &ws[(0 + half * 4 + q) * 1024];
        wr_[q] = &ws[(8 + half * 4 + q) * 1024];
    }
    #pragma unroll
    for (int q = 0; q < 8; ++q) wg_[q] = &ws[(16 + q) * 1024];

    // h pointers (u64, lane-indexed) into each buffer
    const u64* hq1[2] = {
        (const u64*)&bufs[(sub * 16) * 64 + 2 * lane],
        (const u64*)&bufs[TILE_FLOATS + (sub * 16) * 64 + 2 * lane]
    };
    const u64* hq2[2] = {
        (const u64*)&bufs[(w * 8) * 64 + 2 * lane],
        (const u64*)&bufs[TILE_FLOATS + (w * 8) * 64 + 2 * lane]
    };

    for (int t = 0; t < Sz; ++t) {
        const size_t gb = ((size_t)t * Hz + jg) * Bz + bb;
        float gzv = 0.f, grv = 0.f, hv = 0.f, zg = 0.f, rg = 0.f;
        if (w < 8) {
            gzv = g_gates[gb];
            grv = g_gates[plane + gb];
            hv  = g_h[pidx];
        }

        // ================= phase 1: z, r, u = r*h =========================
        u64 az[4] = {0,0,0,0}, ar[4] = {0,0,0,0};
        #pragma unroll
        for (int c = 0; c < 4; ++c)
            cpa16(buf_s[0] + cp_off + c * 8192u, (const char*)g_h + cp_off + c * 8192u);
        cpa_commit();
        #pragma unroll
        for (int tl = 0; tl < 4; ++tl) {
            if (tl < 3) {
                const char* src = (const char*)(g_h + (tl + 1) * TILE_FLOATS);
                #pragma unroll
                for (int c = 0; c < 4; ++c)
                    cpa16(buf_s[(tl + 1) & 1] + cp_off + c * 8192u, src + cp_off + c * 8192u);
                cpa_commit();
                cpa_wait<1>();
            } else {
                cpa_wait<0>();
            }
            __syncthreads();
            const int kg = tl * 256 + sub * 32;   // global k offset of this warp's slice
            const u64* hb = hq1[tl & 1];
            #pragma unroll
            for (int ii = 0; ii < 8; ++ii) {
                u64 hA = hb[(2 * ii + 0) * 32];
                u64 hB = hb[(2 * ii + 1) * 32];
                #pragma unroll
                for (int q = 0; q < 4; ++q) {
                    ulonglong2 qz = ((const ulonglong2*)(wz_[q] + kg))[ii];
                    ulonglong2 qr = ((const ulonglong2*)(wr_[q] + kg))[ii];
                    ffma2(az[q], qz.x, hA); ffma2(az[q], qz.y, hB);
                    ffma2(ar[q], qr.x, hA); ffma2(ar[q], qr.y, hB);
                }
            }
            __syncthreads();
        }
        #pragma unroll
        for (int q = 0; q < 4; ++q) {
            part[(w * 8 + q) * 32 + lane]     = f2sum(az[q]);
            part[(w * 8 + 4 + q) * 32 + lane] = f2sum(ar[q]);
        }
        __syncthreads();

        if (w < 8) {
            const int rh = jr >> 2, jl = jr & 3;
            float zsum = 0.f, rsum = 0.f;
            #pragma unroll
            for (int sb = 0; sb < 8; ++sb) {
                int wi = sb * 2 + rh;
                zsum += part[(wi * 8 + jl) * 32 + bb];
                rsum += part[(wi * 8 + 4 + jl) * 32 + bb];
            }
            zg = sigmoidf_(zsum + gzv + bzj);
            rg = sigmoidf_(rsum + grv + brj);
            g_u[pidx] = rg * hv;
        }

        grid_bar(2 * t, ncta);

        float ggv = 0.f;
        if (w < 8) ggv = g_gates[2 * plane + gb];

        // ================= phase 2: g, h_new ==============================
        u64 ag[8] = {0,0,0,0,0,0,0,0};
        #pragma unroll
        for (int c = 0; c < 4; ++c)
            cpa16(buf_s[0] + cp_off + c * 8192u, (const char*)g_u + cp_off + c * 8192u);
        cpa_commit();
        #pragma unroll
        for (int tl = 0; tl < 4; ++tl) {
            if (tl < 3) {
                const char* src = (const char*)(g_u + (tl + 1) * TILE_FLOATS);
                #pragma unroll
                for (int c = 0; c < 4; ++c)
                    cpa16(buf_s[(tl + 1) & 1] + cp_off + c * 8192u, src + cp_off + c * 8192u);
                cpa_commit();
                cpa_wait<1>();
            } else {
                cpa_wait<0>();
            }
            __syncthreads();
            const int kg = tl * 256 + w * 16;     // this warp's 16-k slice
            const u64* hb = hq2[tl & 1];
            #pragma unroll
            for (int ii = 0; ii < 4; ++ii) {
                u64 hA = hb[(2 * ii + 0) * 32];
                u64 hB = hb[(2 * ii + 1) * 32];
                #pragma unroll
                for (int q = 0; q < 8; ++q) {
                    ulonglong2 qg = ((const ulonglong2*)(wg_[q] + kg))[ii];
                    ffma2(ag[q], qg.x, hA); ffma2(ag[q], qg.y, hB);
                }
            }
            __syncthreads();
        }
        #pragma unroll
        for (int q = 0; q < 8; ++q)
            part[(w * 8 + q) * 32 + lane] = f2sum(ag[q]);
        __syncthreads();

        if (w < 8) {
            float gsum = 0.f;
            #pragma unroll
            for (int sb = 0; sb < 16; ++sb)
                gsum += part[(sb * 8 + jr) * 32 + bb];
            float gv = tanhf(gsum + ggv + bgj);
            float hn = zg * hv + (1.0f - zg) * gv;
            g_h[pidx] = hn;
            g_seq[gb] = hn;
            if (t == Sz - 1) hid_out[bb * (2 * Hz) + layer * Hz + jg] = hn;
        }

        grid_bar(2 * t + 1, ncta);
    }
}

// ---------------------------------------------------------------------------
// projY: y[b][s][o] = sum_h seq[s][h][b] * Wy[o][h] + by[o]
// ---------------------------------------------------------------------------
__global__ void __launch_bounds__(TPB) projy_kernel(
    const float* __restrict__ Wy, const float* __restrict__ by, float* __restrict__ y)
{
    __shared__ float xs[256 * 33];
    const int s = blockIdx.x;
    const int tid = threadIdx.x, lane = tid & 31, w = tid >> 5;

    float acc[16];
    #pragma unroll
    for (int q = 0; q < 16; ++q) acc[q] = 0.f;

    for (int kt = 0; kt < 4; ++kt) {
        __syncthreads();
        #pragma unroll
        for (int rep = 0; rep < 32; ++rep) {
            int e = rep * 256 + tid;
            int i = e >> 5, b = e & 31;
            xs[i * 33 + b] = g_seq[((size_t)s * Hz + kt * 256 + i) * Bz + b];
        }
        __syncthreads();
        #pragma unroll
        for (int c = 0; c < 4; ++c) {
            int o = w * 16 + c * 4;
            const float4* w0 = (const float4*)(Wy + (size_t)(o + 0) * Hz + kt * 256);
            const float4* w1 = (const float4*)(Wy + (size_t)(o + 1) * Hz + kt * 256);
            const float4* w2 = (const float4*)(Wy + (size_t)(o + 2) * Hz + kt * 256);
            const float4* w3 = (const float4*)(Wy + (size_t)(o + 3) * Hz + kt * 256);
            float a0 = acc[c * 4 + 0], a1 = acc[c * 4 + 1];
            float a2 = acc[c * 4 + 2], a3 = acc[c * 4 + 3];
            #pragma unroll 8
            for (int i4 = 0; i4 < 64; ++i4) {
                float h0v = xs[(i4 * 4 + 0) * 33 + lane];
                float h1v = xs[(i4 * 4 + 1) * 33 + lane];
                float h2v = xs[(i4 * 4 + 2) * 33 + lane];
                float h3v = xs[(i4 * 4 + 3) * 33 + lane];
                float4 q0 = w0[i4], q1 = w1[i4], q2 = w2[i4], q3 = w3[i4];
                a0 = fmaf(q0.x, h0v, a0); a0 = fmaf(q0.y, h1v, a0); a0 = fmaf(q0.z, h2v, a0); a0 = fmaf(q0.w, h3v, a0);
                a1 = fmaf(q1.x, h0v, a1); a1 = fmaf(q1.y, h1v, a1); a1 = fmaf(q1.z, h2v, a1); a1 = fmaf(q1.w, h3v, a1);
                a2 = fmaf(q2.x, h0v, a2); a2 = fmaf(q2.y, h1v, a2); a2 = fmaf(q2.z, h2v, a2); a2 = fmaf(q2.w, h3v, a2);
                a3 = fmaf(q3.x, h0v, a3); a3 = fmaf(q3.y, h1v, a3); a3 = fmaf(q3.z, h2v, a3); a3 = fmaf(q3.w, h3v, a3);
            }
            acc[c * 4 + 0] = a0; acc[c * 4 + 1] = a1;
            acc[c * 4 + 2] = a2; acc[c * 4 + 3] = a3;
        }
    }
    #pragma unroll
    for (int c = 0; c < 4; ++c) {
        #pragma unroll
        for (int q = 0; q < 4; ++q) {
            int o = w * 16 + c * 4 + q;
            y[(size_t)lane * (Sz * Oz) + (size_t)s * Oz + o] = acc[c * 4 + q] + by[o];
        }
    }
}

// ---------------------------------------------------------------------------
extern "C" void kernel_launch(void* const* d_in, const int* in_sizes, int n_in,
                              void* d_out, int out_size) {
    (void)in_sizes; (void)n_in; (void)out_size;
    const float* x    = (const float*)d_in[0];
    const float* h0   = (const float*)d_in[1];
    const float* Wxz0 = (const float*)d_in[2];
    const float* Whz0 = (const float*)d_in[3];
    const float* bz0  = (const float*)d_in[4];
    const float* Wxr0 = (const float*)d_in[5];
    const float* Whr0 = (const float*)d_in[6];
    const float* br0  = (const float*)d_in[7];
    const float* Wxg0 = (const float*)d_in[8];
    const float* Whg0 = (const float*)d_in[9];
    const float* bg0  = (const float*)d_in[10];
    const float* Wxz1 = (const float*)d_in[11];
    const float* Whz1 = (const float*)d_in[12];
    const float* bz1  = (const float*)d_in[13];
    const float* Wxr1 = (const float*)d_in[14];
    const float* Whr1 = (const float*)d_in[15];
    const float* br1  = (const float*)d_in[16];
    const float* Wxg1 = (const float*)d_in[17];
    const float* Whg1 = (const float*)d_in[18];
    const float* bg1  = (const float*)d_in[19];
    const float* Wy   = (const float*)d_in[20];
    const float* by   = (const float*)d_in[21];

    float* y   = (float*)d_out;
    float* hid = (float*)d_out + (size_t)Bz * Sz * Oz;

    const int scan_smem = SCAN_SMEM_FLOATS * (int)sizeof(float);
    cudaFuncSetAttribute(scan_kernel, cudaFuncAttributeMaxDynamicSharedMemorySize, scan_smem);

    // Layer 0
    proj0_kernel<<<Sz, TPB>>>(x, Wxz0, Wxr0, Wxg0);
    prep_kernel<<<SCAN_GRID, TPB>>>(h0, 0);
    scan_kernel<<<SCAN_GRID, TPBS, scan_smem>>>(Whz0, Whr0, Whg0, bz0, br0, bg0, hid, 0);

    // Layer 1
    proj1_kernel<<<dim3(8, Sz), TPB>>>(Wxz1, Wxr1, Wxg1);
    prep_kernel<<<SCAN_GRID, TPB>>>(h0, 1);
    scan_kernel<<<SCAN_GRID, TPBS, scan_smem>>>(Whz1, Whr1, Whg1, bz1, br1, bg1, hid, 1);

    // Output head
    projy_kernel<<<Sz, TPB>>>(Wy, by, y);
}